// round 7
// baseline (speedup 1.0000x reference)
#include <cuda_runtime.h>
#include <cstdint>
#include <cstddef>

#define NN 8192
#define KCH 32
#define NCHUNK (NN / KCH)

// ---------------- scratch (no allocations allowed) ----------------
__device__ float g_X1[NN * 128];
__device__ float g_X2[NN * 128];
__device__ float g_P[NN * 128];
__device__ float g_Q[NN * 128];
__device__ float g_U1[NN * 128];
__device__ float g_ptok[NN * 48];   // tok padded: [k][m*16+t], t<10 valid, else 0

// ---------------- helpers ----------------
__device__ __forceinline__ uint32_t f2tf32(float f) {
    uint32_t u;
    asm("cvt.rna.tf32.f32 %0, %1;" : "=r"(u) : "f"(f));
    return u;
}
__device__ __forceinline__ void cp16(float* s, const float* g) {
    uint32_t sa = (uint32_t)__cvta_generic_to_shared(s);
    asm volatile("cp.async.cg.shared.global [%0], [%1], 16;" :: "r"(sa), "l"(g));
}
__device__ __forceinline__ void cp_commit() { asm volatile("cp.async.commit_group;"); }
template <int n> __device__ __forceinline__ void cp_wait() {
    asm volatile("cp.async.wait_group %0;" :: "n"(n));
}
// c += A(16x8 tf32) * B(8x8 tf32), fp32 accum
__device__ __forceinline__ void mma8(float* c, const uint32_t* a, uint32_t b0, uint32_t b1) {
    asm volatile(
        "mma.sync.aligned.m16n8k8.row.col.f32.tf32.tf32.f32 "
        "{%0,%1,%2,%3},{%4,%5,%6,%7},{%8,%9},{%0,%1,%2,%3};"
        : "+f"(c[0]), "+f"(c[1]), "+f"(c[2]), "+f"(c[3])
        : "r"(a[0]), "r"(a[1]), "r"(a[2]), "r"(a[3]), "r"(b0), "r"(b1));
}

// ---------------- tok packer ----------------
__global__ void pack_tok_k(const float* __restrict__ t1, const float* __restrict__ t2,
                           const float* __restrict__ t3) {
    int idx = blockIdx.x * 256 + threadIdx.x;
    if (idx >= NN * 48) return;
    int k = idx / 48, c = idx % 48, m = c >> 4, t = c & 15;
    const float* src = (m == 0) ? t1 : (m == 1) ? t2 : t3;
    g_ptok[idx] = (t < 10) ? src[k * 10 + t] : 0.0f;
}

// ---------------- small exact fp32 GEMM: C[8192x128] = A[8192xK] @ B[Kx128] ----------------
template <int K>
__global__ void __launch_bounds__(256)
gemm_nn_128(const float* __restrict__ A, const float* __restrict__ B, float* __restrict__ C) {
    __shared__ float As[16][68];
    __shared__ float Bs[16][132];
    int tid = threadIdx.x;
    int m0 = blockIdx.x * 64;
    int tx = tid % 16, ty = tid / 16;
    float acc[4][8] = {};
    for (int k0 = 0; k0 < K; k0 += 16) {
        {
            int kk = tid % 16, mm = tid / 16;
#pragma unroll
            for (int p = 0; p < 4; p++) {
                int m = mm + p * 16;
                As[kk][m] = A[(size_t)(m0 + m) * K + k0 + kk];
            }
        }
        {
            int n = tid % 128, kk2 = tid / 128;
#pragma unroll
            for (int p = 0; p < 8; p++)
                Bs[kk2 + p * 2][n] = B[(size_t)(k0 + kk2 + p * 2) * 128 + n];
        }
        __syncthreads();
#pragma unroll
        for (int kk = 0; kk < 16; kk++) {
            float a[4], b[8];
#pragma unroll
            for (int i = 0; i < 4; i++) a[i] = As[kk][ty * 4 + i];
#pragma unroll
            for (int j = 0; j < 8; j++) b[j] = Bs[kk][tx * 8 + j];
#pragma unroll
            for (int i = 0; i < 4; i++)
#pragma unroll
                for (int j = 0; j < 8; j++) acc[i][j] = fmaf(a[i], b[j], acc[i][j]);
        }
        __syncthreads();
    }
#pragma unroll
    for (int i = 0; i < 4; i++) {
        size_t m = (size_t)(m0 + ty * 4 + i);
#pragma unroll
        for (int j = 0; j < 8; j++) C[m * 128 + tx * 8 + j] = acc[i][j];
    }
}

// ---------------- big row sweep: P = temp @ X  (+ fused F_k = A_k @ tok_k) ----------------
// smem layout (floats): A tiles (buf,m): (buf*3+m)*2304  [64 rows x stride 36]
//                       X tile: 13824 + buf*4352         [32 x stride 136]
//                       tok tile: 22528 + buf*1792       [32 x stride 56]
#define ROW_SMEM (26112 * 4)
#define COL_SMEM (22528 * 4)

template <bool FUSE>
__global__ void __launch_bounds__(256)
row_gemm(const float* __restrict__ A1, const float* __restrict__ A2,
         const float* __restrict__ A3, const float* __restrict__ X,
         const float* __restrict__ wb, float* __restrict__ P, float* __restrict__ F) {
    extern __shared__ float sm[];
    const int tid = threadIdx.x, lane = tid & 31, warp = tid >> 5;
    const int row0 = blockIdx.x * 64;
    const int wm = (warp & 3) * 16, wn = (warp >> 2) * 64;
    const int r = lane >> 2, q = lane & 3;
    const float w0 = wb[0], w1 = wb[1], w2 = wb[2];

    float acc[8][4] = {};
    float facc[3][2][4] = {};

    auto load = [&](int buf, int k0) {
#pragma unroll
        for (int it = 0; it < 6; it++) {
            int idx = tid + it * 256;
            int m = idx >> 9, rem = idx & 511;
            int row = rem >> 3, c = rem & 7;
            const float* ap = (m == 0) ? A1 : (m == 1) ? A2 : A3;
            cp16(sm + (buf * 3 + m) * 2304 + row * 36 + c * 4,
                 ap + (size_t)(row0 + row) * NN + k0 + c * 4);
        }
#pragma unroll
        for (int it = 0; it < 4; it++) {
            int idx = tid + it * 256;
            int row = idx >> 5, c = idx & 31;
            cp16(sm + 13824 + buf * 4352 + row * 136 + c * 4,
                 X + (size_t)(k0 + row) * 128 + c * 4);
        }
        if (FUSE) {
#pragma unroll
            for (int it = 0; it < 2; it++) {
                int idx = tid + it * 256;
                if (idx < 384) {
                    int row = idx / 12, c = idx % 12;
                    cp16(sm + 22528 + buf * 1792 + row * 56 + c * 4,
                         g_ptok + (size_t)(k0 + row) * 48 + c * 4);
                }
            }
        }
        cp_commit();
    };

    load(0, 0);
#pragma unroll 1
    for (int ch = 0; ch < NCHUNK; ch++) {
        int buf = ch & 1;
        if (ch + 1 < NCHUNK) {
            load(buf ^ 1, (ch + 1) * KCH);
            cp_wait<1>();
        } else {
            cp_wait<0>();
        }
        __syncthreads();
        const float* sa0 = sm + (buf * 3 + 0) * 2304;
        const float* sa1 = sm + (buf * 3 + 1) * 2304;
        const float* sa2 = sm + (buf * 3 + 2) * 2304;
        const float* sx = sm + 13824 + buf * 4352;
        const float* st = sm + 22528 + buf * 1792;
#pragma unroll
        for (int ks = 0; ks < 4; ks++) {
            int kb = ks * 8;
            int i0 = (wm + r) * 36 + kb + q;
            int i1 = (wm + r + 8) * 36 + kb + q;
            float af[3][4];
            af[0][0] = sa0[i0]; af[0][1] = sa0[i1]; af[0][2] = sa0[i0 + 4]; af[0][3] = sa0[i1 + 4];
            af[1][0] = sa1[i0]; af[1][1] = sa1[i1]; af[1][2] = sa1[i0 + 4]; af[1][3] = sa1[i1 + 4];
            af[2][0] = sa2[i0]; af[2][1] = sa2[i1]; af[2][2] = sa2[i0 + 4]; af[2][3] = sa2[i1 + 4];
            uint32_t ta[4];
#pragma unroll
            for (int i = 0; i < 4; i++)
                ta[i] = f2tf32(fmaf(w2, af[2][i], fmaf(w1, af[1][i], w0 * af[0][i])));
#pragma unroll
            for (int nt = 0; nt < 8; nt++) {
                int n = wn + nt * 8 + r;
                uint32_t b0 = f2tf32(sx[(kb + q) * 136 + n]);
                uint32_t b1 = f2tf32(sx[(kb + q + 4) * 136 + n]);
                mma8(acc[nt], ta, b0, b1);
            }
            if (FUSE && warp < 4) {
#pragma unroll
                for (int m = 0; m < 3; m++) {
                    uint32_t am[4];
#pragma unroll
                    for (int i = 0; i < 4; i++) am[i] = f2tf32(af[m][i]);
#pragma unroll
                    for (int nt = 0; nt < 2; nt++) {
                        int col = m * 16 + nt * 8 + r;
                        uint32_t b0 = f2tf32(st[(kb + q) * 56 + col]);
                        uint32_t b1 = f2tf32(st[(kb + q + 4) * 56 + col]);
                        mma8(facc[m][nt], am, b0, b1);
                    }
                }
            }
        }
        __syncthreads();
    }
    // epilogue: P
#pragma unroll
    for (int nt = 0; nt < 8; nt++) {
        int n = wn + nt * 8 + q * 2;
        float2 v0 = {acc[nt][0], acc[nt][1]};
        float2 v1 = {acc[nt][2], acc[nt][3]};
        *(float2*)&P[(size_t)(row0 + wm + r) * 128 + n] = v0;
        *(float2*)&P[(size_t)(row0 + wm + r + 8) * 128 + n] = v1;
    }
    if (FUSE && warp < 4) {
#pragma unroll
        for (int m = 0; m < 3; m++) {
            float* Fm = F + (size_t)m * NN * 10;
#pragma unroll
            for (int nt = 0; nt < 2; nt++) {
                int t = nt * 8 + q * 2;
                size_t ra = (size_t)(row0 + wm + r) * 10;
                size_t rb = (size_t)(row0 + wm + r + 8) * 10;
                if (t < 10) { Fm[ra + t] = facc[m][nt][0]; Fm[rb + t] = facc[m][nt][2]; }
                if (t + 1 < 10) { Fm[ra + t + 1] = facc[m][nt][1]; Fm[rb + t + 1] = facc[m][nt][3]; }
            }
        }
    }
}

// ---------------- big col sweep: Q = temp^T @ X ----------------
// smem: A tiles (buf,m): (buf*3+m)*2304  [32 j-rows x stride 72 (64 cols)]
//       X tile: 13824 + buf*4352
__global__ void __launch_bounds__(256)
col_gemm(const float* __restrict__ A1, const float* __restrict__ A2,
         const float* __restrict__ A3, const float* __restrict__ X,
         const float* __restrict__ wb, float* __restrict__ Q) {
    extern __shared__ float sm[];
    const int tid = threadIdx.x, lane = tid & 31, warp = tid >> 5;
    const int c0 = blockIdx.x * 64;
    const int wm = (warp & 3) * 16, wn = (warp >> 2) * 64;
    const int r = lane >> 2, q = lane & 3;
    const float w0 = wb[0], w1 = wb[1], w2 = wb[2];

    float acc[8][4] = {};

    auto load = [&](int buf, int j0) {
#pragma unroll
        for (int it = 0; it < 6; it++) {
            int idx = tid + it * 256;
            int m = idx >> 9, rem = idx & 511;
            int row = rem >> 4, c = rem & 15;
            const float* ap = (m == 0) ? A1 : (m == 1) ? A2 : A3;
            cp16(sm + (buf * 3 + m) * 2304 + row * 72 + c * 4,
                 ap + (size_t)(j0 + row) * NN + c0 + c * 4);
        }
#pragma unroll
        for (int it = 0; it < 4; it++) {
            int idx = tid + it * 256;
            int row = idx >> 5, c = idx & 31;
            cp16(sm + 13824 + buf * 4352 + row * 136 + c * 4,
                 X + (size_t)(j0 + row) * 128 + c * 4);
        }
        cp_commit();
    };

    load(0, 0);
#pragma unroll 1
    for (int ch = 0; ch < NCHUNK; ch++) {
        int buf = ch & 1;
        if (ch + 1 < NCHUNK) {
            load(buf ^ 1, (ch + 1) * KCH);
            cp_wait<1>();
        } else {
            cp_wait<0>();
        }
        __syncthreads();
        const float* sa0 = sm + (buf * 3 + 0) * 2304;
        const float* sa1 = sm + (buf * 3 + 1) * 2304;
        const float* sa2 = sm + (buf * 3 + 2) * 2304;
        const float* sx = sm + 13824 + buf * 4352;
#pragma unroll
        for (int ks = 0; ks < 4; ks++) {
            int kb = ks * 8;
            int i0 = (kb + q) * 72 + wm + r;       // temp[j=kb+q][i=wm+r]
            int i1 = (kb + q + 4) * 72 + wm + r;
            float af[3][4];
            af[0][0] = sa0[i0]; af[0][1] = sa0[i0 + 8]; af[0][2] = sa0[i1]; af[0][3] = sa0[i1 + 8];
            af[1][0] = sa1[i0]; af[1][1] = sa1[i0 + 8]; af[1][2] = sa1[i1]; af[1][3] = sa1[i1 + 8];
            af[2][0] = sa2[i0]; af[2][1] = sa2[i0 + 8]; af[2][2] = sa2[i1]; af[2][3] = sa2[i1 + 8];
            uint32_t ta[4];
#pragma unroll
            for (int i = 0; i < 4; i++)
                ta[i] = f2tf32(fmaf(w2, af[2][i], fmaf(w1, af[1][i], w0 * af[0][i])));
#pragma unroll
            for (int nt = 0; nt < 8; nt++) {
                int n = wn + nt * 8 + r;
                uint32_t b0 = f2tf32(sx[(kb + q) * 136 + n]);
                uint32_t b1 = f2tf32(sx[(kb + q + 4) * 136 + n]);
                mma8(acc[nt], ta, b0, b1);
            }
        }
        __syncthreads();
    }
#pragma unroll
    for (int nt = 0; nt < 8; nt++) {
        int n = wn + nt * 8 + q * 2;
        float2 v0 = {acc[nt][0], acc[nt][1]};
        float2 v1 = {acc[nt][2], acc[nt][3]};
        *(float2*)&Q[(size_t)(c0 + wm + r) * 128 + n] = v0;
        *(float2*)&Q[(size_t)(c0 + wm + r + 8) * 128 + n] = v1;
    }
}

// ---------------- elementwise ----------------
__global__ void u1_k(const float* __restrict__ b1) {
    int i = blockIdx.x * 256 + threadIdx.x;
    g_U1[i] = g_P[i] + g_Q[i] + b1[i & 127];
}
__global__ void out_k(const float* __restrict__ b2, float* __restrict__ out) {
    int i = blockIdx.x * 256 + threadIdx.x;
    out[i] = 0.5f * (g_U1[i] + (g_P[i] + g_Q[i] + b2[i & 127]));
}

// ---------------- launch ----------------
extern "C" void kernel_launch(void* const* d_in, const int* in_sizes, int n_in,
                              void* d_out, int out_size) {
    const float* feature = (const float*)d_in[0];
    const float* A1 = (const float*)d_in[1];
    const float* A2 = (const float*)d_in[2];
    const float* A3 = (const float*)d_in[3];
    const float* t1 = (const float*)d_in[4];
    const float* t2 = (const float*)d_in[5];
    const float* t3 = (const float*)d_in[6];
    const float* wb = (const float*)d_in[7];
    const float* W1 = (const float*)d_in[8];
    const float* b1 = (const float*)d_in[9];
    const float* W2 = (const float*)d_in[10];
    const float* b2 = (const float*)d_in[11];
    float* out = (float*)d_out;

    float *X1p, *X2p, *Pp, *Qp, *U1p;
    cudaGetSymbolAddress((void**)&X1p, g_X1);
    cudaGetSymbolAddress((void**)&X2p, g_X2);
    cudaGetSymbolAddress((void**)&Pp, g_P);
    cudaGetSymbolAddress((void**)&Qp, g_Q);
    cudaGetSymbolAddress((void**)&U1p, g_U1);

    cudaFuncSetAttribute(row_gemm<true>, cudaFuncAttributeMaxDynamicSharedMemorySize, ROW_SMEM);
    cudaFuncSetAttribute(row_gemm<false>, cudaFuncAttributeMaxDynamicSharedMemorySize, ROW_SMEM);
    cudaFuncSetAttribute(col_gemm, cudaFuncAttributeMaxDynamicSharedMemorySize, COL_SMEM);

    pack_tok_k<<<(NN * 48 + 255) / 256, 256>>>(t1, t2, t3);
    gemm_nn_128<256><<<128, 256>>>(feature, W1, X1p);
    row_gemm<true><<<128, 256, ROW_SMEM>>>(A1, A2, A3, X1p, wb, Pp, out + (size_t)NN * 128);
    col_gemm<<<128, 256, COL_SMEM>>>(A1, A2, A3, X1p, wb, Qp);
    u1_k<<<4096, 256>>>(b1);
    gemm_nn_128<128><<<128, 256>>>(U1p, W2, X2p);
    row_gemm<false><<<128, 256, ROW_SMEM>>>(A1, A2, A3, X2p, wb, Pp, nullptr);
    col_gemm<<<128, 256, COL_SMEM>>>(A1, A2, A3, X2p, wb, Qp);
    out_k<<<4096, 256>>>(b2, out);
}

// round 10
// speedup vs baseline: 2.8400x; 2.8400x over previous
#include <cuda_runtime.h>
#include <cuda_fp16.h>
#include <cstdint>
#include <cstddef>

#define NN 8192
#define NM (NN * 128)

// K1 (stage-1 row sweep over A): chunking
#define KCH1 32
#define NCH1 (NN / KCH1)
// fp16 temp sweeps
#define SEGK 4096
#define KCH2 64
#define NCH2 (SEGK / KCH2)

// ---------------- scratch (no allocations allowed) ----------------
__device__ float  g_X1[NM];
__device__ float  g_X2[NM];
__device__ float  g_U1[NM];
__device__ float  g_P1[NM];
__device__ float  g_Qp[2 * NM];
__device__ float  g_Pp[2 * NM];
__device__ __half g_XhT1[128 * NN];
__device__ __half g_XhT2[128 * NN];
__device__ __half g_temph[(size_t)NN * NN];      // 128 MB
__device__ float  g_ptok[NN * 48];               // tok padded [k][m*16+t]

// ---------------- helpers ----------------
__device__ __forceinline__ uint32_t f2tf32(float f) {
    uint32_t u;
    asm("cvt.rna.tf32.f32 %0, %1;" : "=r"(u) : "f"(f));
    return u;
}
__device__ __forceinline__ void cp16(void* s, const void* g) {
    uint32_t sa = (uint32_t)__cvta_generic_to_shared(s);
    asm volatile("cp.async.cg.shared.global [%0], [%1], 16;" :: "r"(sa), "l"(g));
}
__device__ __forceinline__ void cp_commit() { asm volatile("cp.async.commit_group;"); }
template <int n> __device__ __forceinline__ void cp_wait() {
    asm volatile("cp.async.wait_group %0;" :: "n"(n));
}
// tf32 mma (fused F path)
__device__ __forceinline__ void mma8(float* c, const uint32_t* a, uint32_t b0, uint32_t b1) {
    asm volatile(
        "mma.sync.aligned.m16n8k8.row.col.f32.tf32.tf32.f32 "
        "{%0,%1,%2,%3},{%4,%5,%6,%7},{%8,%9},{%0,%1,%2,%3};"
        : "+f"(c[0]), "+f"(c[1]), "+f"(c[2]), "+f"(c[3])
        : "r"(a[0]), "r"(a[1]), "r"(a[2]), "r"(a[3]), "r"(b0), "r"(b1));
}
// fp16 mma m16n8k16, fp32 accum
__device__ __forceinline__ void mma16(float* c, const uint32_t* a, uint32_t b0, uint32_t b1) {
    asm volatile(
        "mma.sync.aligned.m16n8k16.row.col.f32.f16.f16.f32 "
        "{%0,%1,%2,%3},{%4,%5,%6,%7},{%8,%9},{%0,%1,%2,%3};"
        : "+f"(c[0]), "+f"(c[1]), "+f"(c[2]), "+f"(c[3])
        : "r"(a[0]), "r"(a[1]), "r"(a[2]), "r"(a[3]), "r"(b0), "r"(b1));
}

// ---------------- tok packer ----------------
__global__ void pack_tok_k(const float* __restrict__ t1, const float* __restrict__ t2,
                           const float* __restrict__ t3) {
    int idx = blockIdx.x * 256 + threadIdx.x;
    if (idx >= NN * 48) return;
    int k = idx / 48, c = idx % 48, m = c >> 4, t = c & 15;
    const float* src = (m == 0) ? t1 : (m == 1) ? t2 : t3;
    g_ptok[idx] = (t < 10) ? src[k * 10 + t] : 0.0f;
}

// ---------------- exact fp32 GEMM: C[8192x128] = A[8192xK] @ B[Kx128] ----------------
template <int K>
__global__ void __launch_bounds__(256)
gemm_nn_128(const float* __restrict__ A, const float* __restrict__ B, float* __restrict__ C) {
    __shared__ float As[16][68];
    __shared__ float Bs[16][132];
    int tid = threadIdx.x;
    int m0 = blockIdx.x * 64;
    int tx = tid % 16, ty = tid / 16;
    float acc[4][8] = {};
    for (int k0 = 0; k0 < K; k0 += 16) {
        {
            int kk = tid % 16, mm = tid / 16;
#pragma unroll
            for (int p = 0; p < 4; p++) {
                int m = mm + p * 16;
                As[kk][m] = A[(size_t)(m0 + m) * K + k0 + kk];
            }
        }
        {
            int n = tid % 128, kk2 = tid / 128;
#pragma unroll
            for (int p = 0; p < 8; p++)
                Bs[kk2 + p * 2][n] = B[(size_t)(k0 + kk2 + p * 2) * 128 + n];
        }
        __syncthreads();
#pragma unroll
        for (int kk = 0; kk < 16; kk++) {
            float a[4], b[8];
#pragma unroll
            for (int i = 0; i < 4; i++) a[i] = As[kk][ty * 4 + i];
#pragma unroll
            for (int j = 0; j < 8; j++) b[j] = Bs[kk][tx * 8 + j];
#pragma unroll
            for (int i = 0; i < 4; i++)
#pragma unroll
                for (int j = 0; j < 8; j++) acc[i][j] = fmaf(a[i], b[j], acc[i][j]);
        }
        __syncthreads();
    }
#pragma unroll
    for (int i = 0; i < 4; i++) {
        size_t m = (size_t)(m0 + ty * 4 + i);
#pragma unroll
        for (int j = 0; j < 8; j++) C[m * 128 + tx * 8 + j] = acc[i][j];
    }
}

// ---------------- transpose+convert: XhT[n][k] = (half)X[k][n] ----------------
__global__ void xt_k(const float* __restrict__ X, __half* __restrict__ XT) {
    __shared__ float t[32][33];
    int k0 = blockIdx.x * 32, n0 = blockIdx.y * 32;
    int tx = threadIdx.x, ty = threadIdx.y;   // 32 x 8
#pragma unroll
    for (int i = 0; i < 4; i++)
        t[ty + i * 8][tx] = X[(size_t)(k0 + ty + i * 8) * 128 + n0 + tx];
    __syncthreads();
#pragma unroll
    for (int i = 0; i < 4; i++)
        XT[(size_t)(n0 + ty + i * 8) * NN + k0 + tx] = __float2half_rn(t[tx][ty + i * 8]);
}

// =============== K1: stage-1 row sweep ===============
// Reads A1..A3 row stripes; writes temp fp16 to global; P1 = temp@X (fp16 mma);
// fused F_k = A_k@tok_k (tf32, warps 0-3).
#define K1_SMEM 140288

__global__ void __launch_bounds__(256)
row1_k(const float* __restrict__ A1, const float* __restrict__ A2,
       const float* __restrict__ A3, const __half* __restrict__ XhT,
       const float* __restrict__ wb, float* __restrict__ P,
       float* __restrict__ F, __half* __restrict__ Tout) {
    extern __shared__ char sm[];
    const int tid = threadIdx.x, lane = tid & 31, warp = tid >> 5;
    const int row0 = blockIdx.x * 64;
    const int wm = (warp & 3) * 16, wn = (warp >> 2) * 64;
    const int r = lane >> 2, q = lane & 3;
    const float w0 = wb[0], w1 = wb[1], w2 = wb[2];

    float acc[8][4] = {};
    float facc[3][2][4] = {};

    auto smA = [&](int s, int m) { return (float*)sm + (s * 3 + m) * 2304; };
    auto smTok = [&](int s) { return (float*)(sm + 82944) + s * 1792; };
    auto smX = [&](int s) { return (__half*)(sm + 104448) + s * 5120; };
    __half* tempH = (__half*)(sm + 135168);

    auto load = [&](int s, int k0) {
#pragma unroll
        for (int it = 0; it < 6; it++) {
            int idx = tid + it * 256;
            int m = idx >> 9, rem = idx & 511, row = rem >> 3, c = rem & 7;
            const float* ap = (m == 0) ? A1 : (m == 1) ? A2 : A3;
            cp16(smA(s, m) + row * 36 + c * 4,
                 ap + (size_t)(row0 + row) * NN + k0 + c * 4);
        }
#pragma unroll
        for (int it = 0; it < 2; it++) {
            int idx = tid + it * 256;
            if (idx < 384) {
                int row = idx / 12, c = idx % 12;
                cp16(smTok(s) + row * 56 + c * 4, g_ptok + (size_t)(k0 + row) * 48 + c * 4);
            }
        }
#pragma unroll
        for (int it = 0; it < 2; it++) {
            int idx = tid + it * 256;
            int row = idx >> 2, c = idx & 3;
            cp16(smX(s) + row * 40 + c * 8, XhT + (size_t)row * NN + k0 + c * 8);
        }
        cp_commit();
    };

    load(0, 0);
    load(1, KCH1);
#pragma unroll 1
    for (int ch = 0; ch < NCH1; ch++) {
        int k0 = ch * KCH1;
        if (ch + 2 < NCH1) { load((ch + 2) % 3, (ch + 2) * KCH1); cp_wait<2>(); }
        else if (ch + 1 < NCH1) { cp_wait<1>(); }
        else { cp_wait<0>(); }
        __syncthreads();
        int s = ch % 3;
        const float* sa0 = smA(s, 0);
        const float* sa1 = smA(s, 1);
        const float* sa2 = smA(s, 2);
        const float* st = smTok(s);
        const __half* xs = smX(s);

        // temp = w0*A1 + w1*A2 + w2*A3 -> fp16 smem
        {
            int row = tid >> 2, cb = (tid & 3) * 8;
            const float* p0 = sa0 + row * 36 + cb;
            const float* p1 = sa1 + row * 36 + cb;
            const float* p2 = sa2 + row * 36 + cb;
            __half* th = tempH + row * 40 + cb;
#pragma unroll
            for (int j = 0; j < 4; j++) {
                float u = fmaf(w2, p2[2 * j], fmaf(w1, p1[2 * j], w0 * p0[2 * j]));
                float v = fmaf(w2, p2[2 * j + 1], fmaf(w1, p1[2 * j + 1], w0 * p0[2 * j + 1]));
                *(__half2*)(th + 2 * j) = __floats2half2_rn(u, v);
            }
        }
        __syncthreads();
        // stream temp chunk to global (coalesced 16B stores)
        {
            int row = tid >> 2, cb = (tid & 3) * 8;
            uint4 v = *(const uint4*)(tempH + row * 40 + cb);
            *(uint4*)(Tout + (size_t)(row0 + row) * NN + k0 + cb) = v;
        }
        // P1 mma (fp16)
#pragma unroll
        for (int ks = 0; ks < 2; ks++) {
            int kb = ks * 16;
            uint32_t a[4];
            a[0] = *(const uint32_t*)(tempH + (wm + r) * 40 + kb + q * 2);
            a[1] = *(const uint32_t*)(tempH + (wm + r + 8) * 40 + kb + q * 2);
            a[2] = *(const uint32_t*)(tempH + (wm + r) * 40 + kb + 8 + q * 2);
            a[3] = *(const uint32_t*)(tempH + (wm + r + 8) * 40 + kb + 8 + q * 2);
#pragma unroll
            for (int nt = 0; nt < 8; nt++) {
                int n = wn + nt * 8 + r;
                uint32_t b0 = *(const uint32_t*)(xs + n * 40 + kb + q * 2);
                uint32_t b1 = *(const uint32_t*)(xs + n * 40 + kb + 8 + q * 2);
                mma16(acc[nt], a, b0, b1);
            }
        }
        // fused F_k = A_k @ tok_k (tf32, warps 0-3 cover all 64 rows)
        if (warp < 4) {
#pragma unroll
            for (int ks8 = 0; ks8 < 4; ks8++) {
                int kb = ks8 * 8;
                int i0 = (wm + r) * 36 + kb + q;
                int i1 = (wm + r + 8) * 36 + kb + q;
                float af[3][4];
                af[0][0] = sa0[i0]; af[0][1] = sa0[i1]; af[0][2] = sa0[i0 + 4]; af[0][3] = sa0[i1 + 4];
                af[1][0] = sa1[i0]; af[1][1] = sa1[i1]; af[1][2] = sa1[i0 + 4]; af[1][3] = sa1[i1 + 4];
                af[2][0] = sa2[i0]; af[2][1] = sa2[i1]; af[2][2] = sa2[i0 + 4]; af[2][3] = sa2[i1 + 4];
#pragma unroll
                for (int m = 0; m < 3; m++) {
                    uint32_t am[4];
#pragma unroll
                    for (int i = 0; i < 4; i++) am[i] = f2tf32(af[m][i]);
#pragma unroll
                    for (int nt = 0; nt < 2; nt++) {
                        int col = m * 16 + nt * 8 + r;
                        uint32_t b0 = f2tf32(st[(kb + q) * 56 + col]);
                        uint32_t b1 = f2tf32(st[(kb + q + 4) * 56 + col]);
                        mma8(facc[m][nt], am, b0, b1);
                    }
                }
            }
        }
        __syncthreads();
    }
    // epilogue: P1
#pragma unroll
    for (int nt = 0; nt < 8; nt++) {
        int n = wn + nt * 8 + q * 2;
        float2 v0 = {acc[nt][0], acc[nt][1]};
        float2 v1 = {acc[nt][2], acc[nt][3]};
        *(float2*)&P[(size_t)(row0 + wm + r) * 128 + n] = v0;
        *(float2*)&P[(size_t)(row0 + wm + r + 8) * 128 + n] = v1;
    }
    // epilogue: F
    if (warp < 4) {
#pragma unroll
        for (int m = 0; m < 3; m++) {
            float* Fm = F + (size_t)m * NN * 10;
#pragma unroll
            for (int nt = 0; nt < 2; nt++) {
                int t = nt * 8 + q * 2;
                size_t ra = (size_t)(row0 + wm + r) * 10;
                size_t rb = (size_t)(row0 + wm + r + 8) * 10;
                if (t < 10) { Fm[ra + t] = facc[m][nt][0]; Fm[rb + t] = facc[m][nt][2]; }
                if (t + 1 < 10) { Fm[ra + t + 1] = facc[m][nt][1]; Fm[rb + t + 1] = facc[m][nt][3]; }
            }
        }
    }
}

// =============== fp16 temp sweep: C_part = T(^T) @ Xh over one K segment ===============
#define SW_SMEM (3 * 27648)

template <bool TRANS>
__global__ void __launch_bounds__(256, 2)
sweep_k(const __half* __restrict__ Th, const __half* __restrict__ Xh, float* __restrict__ C) {
    extern __shared__ char sm[];
    const int tid = threadIdx.x, lane = tid & 31, warp = tid >> 5;
    const int m0 = blockIdx.x * 64;
    const int kbase = blockIdx.y * SEGK;
    const int wm = (warp & 3) * 16, wn = (warp >> 2) * 64;
    const int r = lane >> 2, q = lane & 3;
    C += (size_t)blockIdx.y * NM;

    float acc[8][4] = {};
    auto Ts = [&](int s) { return (__half*)(sm + s * 27648); };
    auto Xs = [&](int s) { return (__half*)(sm + s * 27648 + 9216); };

    auto load = [&](int s, int k0) {
        __half* ts = Ts(s);
        __half* xs = Xs(s);
#pragma unroll
        for (int it = 0; it < 2; it++) {
            int idx = tid + it * 256;
            int row = idx >> 3, c = idx & 7;
            const __half* src = TRANS ? Th + (size_t)(k0 + row) * NN + m0 + c * 8
                                      : Th + (size_t)(m0 + row) * NN + k0 + c * 8;
            cp16(ts + row * 72 + c * 8, src);
        }
#pragma unroll
        for (int it = 0; it < 4; it++) {
            int idx = tid + it * 256;
            int row = idx >> 3, c = idx & 7;
            cp16(xs + row * 72 + c * 8, Xh + (size_t)row * NN + k0 + c * 8);
        }
        cp_commit();
    };

    load(0, kbase);
    load(1, kbase + KCH2);
#pragma unroll 1
    for (int ch = 0; ch < NCH2; ch++) {
        if (ch + 2 < NCH2) { load((ch + 2) % 3, kbase + (ch + 2) * KCH2); cp_wait<2>(); }
        else if (ch + 1 < NCH2) { cp_wait<1>(); }
        else { cp_wait<0>(); }
        __syncthreads();
        const __half* ts = Ts(ch % 3);
        const __half* xs = Xs(ch % 3);
#pragma unroll
        for (int ks = 0; ks < 4; ks++) {
            int kb = ks * 16;
            uint32_t a[4];
            if (TRANS) {
                int g = lane >> 3, l8 = lane & 7;
                int rrow = kb + ((g >> 1) << 3) + l8;
                int ccol = wm + ((g & 1) << 3);
                uint32_t addr = (uint32_t)__cvta_generic_to_shared(ts + rrow * 72 + ccol);
                asm volatile(
                    "ldmatrix.sync.aligned.m8n8.x4.trans.shared.b16 {%0,%1,%2,%3}, [%4];"
                    : "=r"(a[0]), "=r"(a[1]), "=r"(a[2]), "=r"(a[3]) : "r"(addr));
            } else {
                a[0] = *(const uint32_t*)(ts + (wm + r) * 72 + kb + q * 2);
                a[1] = *(const uint32_t*)(ts + (wm + r + 8) * 72 + kb + q * 2);
                a[2] = *(const uint32_t*)(ts + (wm + r) * 72 + kb + 8 + q * 2);
                a[3] = *(const uint32_t*)(ts + (wm + r + 8) * 72 + kb + 8 + q * 2);
            }
#pragma unroll
            for (int nt = 0; nt < 8; nt++) {
                int n = wn + nt * 8 + r;
                uint32_t b0 = *(const uint32_t*)(xs + n * 72 + kb + q * 2);
                uint32_t b1 = *(const uint32_t*)(xs + n * 72 + kb + 8 + q * 2);
                mma16(acc[nt], a, b0, b1);
            }
        }
        __syncthreads();
    }
#pragma unroll
    for (int nt = 0; nt < 8; nt++) {
        int n = wn + nt * 8 + q * 2;
        float2 v0 = {acc[nt][0], acc[nt][1]};
        float2 v1 = {acc[nt][2], acc[nt][3]};
        *(float2*)&C[(size_t)(m0 + wm + r) * 128 + n] = v0;
        *(float2*)&C[(size_t)(m0 + wm + r + 8) * 128 + n] = v1;
    }
}

// ---------------- elementwise ----------------
__global__ void u1_k(const float* __restrict__ b1) {
    int i = blockIdx.x * 256 + threadIdx.x;
    g_U1[i] = g_P1[i] + g_Qp[i] + g_Qp[NM + i] + b1[i & 127];
}
__global__ void out_k(const float* __restrict__ b2, float* __restrict__ out) {
    int i = blockIdx.x * 256 + threadIdx.x;
    float u2 = g_Pp[i] + g_Pp[NM + i] + g_Qp[i] + g_Qp[NM + i] + b2[i & 127];
    out[i] = 0.5f * (g_U1[i] + u2);
}

// ---------------- launch ----------------
extern "C" void kernel_launch(void* const* d_in, const int* in_sizes, int n_in,
                              void* d_out, int out_size) {
    (void)in_sizes; (void)n_in; (void)out_size;
    const float* feature = (const float*)d_in[0];
    const float* A1 = (const float*)d_in[1];
    const float* A2 = (const float*)d_in[2];
    const float* A3 = (const float*)d_in[3];
    const float* t1 = (const float*)d_in[4];
    const float* t2 = (const float*)d_in[5];
    const float* t3 = (const float*)d_in[6];
    const float* wb = (const float*)d_in[7];
    const float* W1 = (const float*)d_in[8];
    const float* b1 = (const float*)d_in[9];
    const float* W2 = (const float*)d_in[10];
    const float* b2 = (const float*)d_in[11];
    float* out = (float*)d_out;

    float *X1p, *X2p, *U1p, *P1p, *Qpp, *Ppp;
    __half *XhT1p, *XhT2p, *Tp;
    cudaGetSymbolAddress((void**)&X1p, g_X1);
    cudaGetSymbolAddress((void**)&X2p, g_X2);
    cudaGetSymbolAddress((void**)&U1p, g_U1);
    cudaGetSymbolAddress((void**)&P1p, g_P1);
    cudaGetSymbolAddress((void**)&Qpp, g_Qp);
    cudaGetSymbolAddress((void**)&Ppp, g_Pp);
    cudaGetSymbolAddress((void**)&XhT1p, g_XhT1);
    cudaGetSymbolAddress((void**)&XhT2p, g_XhT2);
    cudaGetSymbolAddress((void**)&Tp, g_temph);

    cudaFuncSetAttribute(row1_k, cudaFuncAttributeMaxDynamicSharedMemorySize, K1_SMEM);
    cudaFuncSetAttribute(sweep_k<true>, cudaFuncAttributeMaxDynamicSharedMemorySize, SW_SMEM);
    cudaFuncSetAttribute(sweep_k<false>, cudaFuncAttributeMaxDynamicSharedMemorySize, SW_SMEM);

    dim3 sg(128, 2);

    pack_tok_k<<<(NN * 48 + 255) / 256, 256>>>(t1, t2, t3);
    gemm_nn_128<256><<<128, 256>>>(feature, W1, X1p);
    xt_k<<<dim3(NN / 32, 4), dim3(32, 8)>>>(X1p, XhT1p);
    // stage 1: row sweep over A (writes temp fp16, P1, F)
    row1_k<<<128, 256, K1_SMEM>>>(A1, A2, A3, XhT1p, wb, P1p, out + (size_t)NM, Tp);
    // stage 1: col sweep over temp fp16 -> Q1 partials
    sweep_k<true><<<sg, 256, SW_SMEM>>>(Tp, XhT1p, Qpp);
    u1_k<<<NM / 256, 256>>>(b1);
    gemm_nn_128<128><<<128, 256>>>(U1p, W2, X2p);
    xt_k<<<dim3(NN / 32, 4), dim3(32, 8)>>>(X2p, XhT2p);
    // stage 2: row + col sweeps over temp fp16 -> P2/Q2 partials
    sweep_k<false><<<sg, 256, SW_SMEM>>>(Tp, XhT2p, Ppp);
    sweep_k<true><<<sg, 256, SW_SMEM>>>(Tp, XhT2p, Qpp);
    out_k<<<NM / 256, 256>>>(b2, out);
}

// round 13
// speedup vs baseline: 2.8774x; 1.0132x over previous
#include <cuda_runtime.h>
#include <cuda_fp16.h>
#include <cstdint>
#include <cstddef>

#define NN 8192
#define NM (NN * 128)

// K1 (stage-1 row sweep over A): 32-row tiles, grid 256
#define KCH1 32
#define NCH1 (NN / KCH1)
// fp16 temp sweeps: 4 K-segments, 2-stage pipeline
#define NSEG 4
#define SEGK (NN / NSEG)
#define KCH2 64
#define NCH2 (SEGK / KCH2)

// ---------------- scratch (no allocations allowed) ----------------
__device__ float  g_X1[NM];
__device__ float  g_X2[NM];
__device__ float  g_U1[NM];
__device__ float  g_P1[NM];
__device__ float  g_Qp[NSEG * NM];
__device__ float  g_Pp[NSEG * NM];
__device__ __half g_XhT1[128 * NN];
__device__ __half g_XhT2[128 * NN];
__device__ __half g_temph[(size_t)NN * NN];      // 128 MB
__device__ float  g_ptok[NN * 48];               // tok padded [k][m*16+t]

// ---------------- helpers ----------------
__device__ __forceinline__ uint32_t f2tf32(float f) {
    uint32_t u;
    asm("cvt.rna.tf32.f32 %0, %1;" : "=r"(u) : "f"(f));
    return u;
}
__device__ __forceinline__ void cp16(void* s, const void* g) {
    uint32_t sa = (uint32_t)__cvta_generic_to_shared(s);
    asm volatile("cp.async.cg.shared.global [%0], [%1], 16;" :: "r"(sa), "l"(g));
}
__device__ __forceinline__ void cp_commit() { asm volatile("cp.async.commit_group;"); }
template <int n> __device__ __forceinline__ void cp_wait() {
    asm volatile("cp.async.wait_group %0;" :: "n"(n));
}
// tf32 mma (fused F path)
__device__ __forceinline__ void mma8(float* c, const uint32_t* a, uint32_t b0, uint32_t b1) {
    asm volatile(
        "mma.sync.aligned.m16n8k8.row.col.f32.tf32.tf32.f32 "
        "{%0,%1,%2,%3},{%4,%5,%6,%7},{%8,%9},{%0,%1,%2,%3};"
        : "+f"(c[0]), "+f"(c[1]), "+f"(c[2]), "+f"(c[3])
        : "r"(a[0]), "r"(a[1]), "r"(a[2]), "r"(a[3]), "r"(b0), "r"(b1));
}
// fp16 mma m16n8k16, fp32 accum
__device__ __forceinline__ void mma16(float* c, const uint32_t* a, uint32_t b0, uint32_t b1) {
    asm volatile(
        "mma.sync.aligned.m16n8k16.row.col.f32.f16.f16.f32 "
        "{%0,%1,%2,%3},{%4,%5,%6,%7},{%8,%9},{%0,%1,%2,%3};"
        : "+f"(c[0]), "+f"(c[1]), "+f"(c[2]), "+f"(c[3])
        : "r"(a[0]), "r"(a[1]), "r"(a[2]), "r"(a[3]), "r"(b0), "r"(b1));
}

// ---------------- tok packer ----------------
__global__ void pack_tok_k(const float* __restrict__ t1, const float* __restrict__ t2,
                           const float* __restrict__ t3) {
    int idx = blockIdx.x * 256 + threadIdx.x;
    if (idx >= NN * 48) return;
    int k = idx / 48, c = idx % 48, m = c >> 4, t = c & 15;
    const float* src = (m == 0) ? t1 : (m == 1) ? t2 : t3;
    g_ptok[idx] = (t < 10) ? src[k * 10 + t] : 0.0f;
}

// ---------------- exact fp32 GEMM: C[8192x128] = A[8192xK] @ B[Kx128] ----------------
template <int K>
__global__ void __launch_bounds__(256)
gemm_nn_128(const float* __restrict__ A, const float* __restrict__ B, float* __restrict__ C) {
    __shared__ float As[16][68];
    __shared__ float Bs[16][132];
    int tid = threadIdx.x;
    int m0 = blockIdx.x * 64;
    int tx = tid % 16, ty = tid / 16;
    float acc[4][8] = {};
    for (int k0 = 0; k0 < K; k0 += 16) {
        {
            int kk = tid % 16, mm = tid / 16;
#pragma unroll
            for (int p = 0; p < 4; p++) {
                int m = mm + p * 16;
                As[kk][m] = A[(size_t)(m0 + m) * K + k0 + kk];
            }
        }
        {
            int n = tid % 128, kk2 = tid / 128;
#pragma unroll
            for (int p = 0; p < 8; p++)
                Bs[kk2 + p * 2][n] = B[(size_t)(k0 + kk2 + p * 2) * 128 + n];
        }
        __syncthreads();
#pragma unroll
        for (int kk = 0; kk < 16; kk++) {
            float a[4], b[8];
#pragma unroll
            for (int i = 0; i < 4; i++) a[i] = As[kk][ty * 4 + i];
#pragma unroll
            for (int j = 0; j < 8; j++) b[j] = Bs[kk][tx * 8 + j];
#pragma unroll
            for (int i = 0; i < 4; i++)
#pragma unroll
                for (int j = 0; j < 8; j++) acc[i][j] = fmaf(a[i], b[j], acc[i][j]);
        }
        __syncthreads();
    }
#pragma unroll
    for (int i = 0; i < 4; i++) {
        size_t m = (size_t)(m0 + ty * 4 + i);
#pragma unroll
        for (int j = 0; j < 8; j++) C[m * 128 + tx * 8 + j] = acc[i][j];
    }
}

// ---------------- transpose+convert: XhT[n][k] = (half)X[k][n] ----------------
__global__ void xt_k(const float* __restrict__ X, __half* __restrict__ XT) {
    __shared__ float t[32][33];
    int k0 = blockIdx.x * 32, n0 = blockIdx.y * 32;
    int tx = threadIdx.x, ty = threadIdx.y;   // 32 x 8
#pragma unroll
    for (int i = 0; i < 4; i++)
        t[ty + i * 8][tx] = X[(size_t)(k0 + ty + i * 8) * 128 + n0 + tx];
    __syncthreads();
#pragma unroll
    for (int i = 0; i < 4; i++)
        XT[(size_t)(n0 + ty + i * 8) * NN + k0 + tx] = __float2half_rn(t[tx][ty + i * 8]);
}

// =============== K1: stage-1 row sweep (32-row tiles, grid 256, 2 CTA/SM) ===============
// smem (bytes): A fp32 tiles: (s*3+m)*4608    [32 x stride 36]      -> 41472
//               tok fp32:     41472 + s*7168  [32 x stride 56]      -> 21504
//               X  fp16:      62976 + s*10240 [128 x stride 40]     -> 30720
//               tempH fp16:   93696           [32 x stride 40]      ->  2560
#define K1_SMEM 96256

__global__ void __launch_bounds__(256, 2)
row1_k(const float* __restrict__ A1, const float* __restrict__ A2,
       const float* __restrict__ A3, const __half* __restrict__ XhT,
       const float* __restrict__ wb, float* __restrict__ P,
       float* __restrict__ F, __half* __restrict__ Tout) {
    extern __shared__ char sm[];
    const int tid = threadIdx.x, lane = tid & 31, warp = tid >> 5;
    const int row0 = blockIdx.x * 32;
    const int wm = (warp & 1) * 16, wn = (warp >> 1) * 32;
    const int r = lane >> 2, q = lane & 3;
    const float w0 = wb[0], w1 = wb[1], w2 = wb[2];

    float acc[4][4] = {};
    float facc[3][2][4] = {};

    auto smA = [&](int s, int m) { return (float*)sm + (s * 3 + m) * 1152; };
    auto smTok = [&](int s) { return (float*)(sm + 41472) + s * 1792; };
    auto smX = [&](int s) { return (__half*)(sm + 62976) + s * 5120; };
    __half* tempH = (__half*)(sm + 93696);

    auto load = [&](int s, int k0) {
#pragma unroll
        for (int it = 0; it < 3; it++) {
            int idx = tid + it * 256;
            int m = idx >> 8, rem = idx & 255, row = rem >> 3, c = rem & 7;
            const float* ap = (m == 0) ? A1 : (m == 1) ? A2 : A3;
            cp16(smA(s, m) + row * 36 + c * 4,
                 ap + (size_t)(row0 + row) * NN + k0 + c * 4);
        }
#pragma unroll
        for (int it = 0; it < 2; it++) {
            int idx = tid + it * 256;
            if (idx < 384) {
                int row = idx / 12, c = idx % 12;
                cp16(smTok(s) + row * 56 + c * 4, g_ptok + (size_t)(k0 + row) * 48 + c * 4);
            }
        }
#pragma unroll
        for (int it = 0; it < 2; it++) {
            int idx = tid + it * 256;
            int row = idx >> 2, c = idx & 3;
            cp16(smX(s) + row * 40 + c * 8, XhT + (size_t)row * NN + k0 + c * 8);
        }
        cp_commit();
    };

    load(0, 0);
    load(1, KCH1);
#pragma unroll 1
    for (int ch = 0; ch < NCH1; ch++) {
        int k0 = ch * KCH1;
        if (ch + 2 < NCH1) { load((ch + 2) % 3, (ch + 2) * KCH1); cp_wait<2>(); }
        else if (ch + 1 < NCH1) { cp_wait<1>(); }
        else { cp_wait<0>(); }
        __syncthreads();
        int s = ch % 3;
        const float* sa0 = smA(s, 0);
        const float* sa1 = smA(s, 1);
        const float* sa2 = smA(s, 2);
        const float* st = smTok(s);
        const __half* xs = smX(s);

        // temp = w0*A1 + w1*A2 + w2*A3 -> fp16 smem (32x32, 4 elems/thread)
        {
            int row = tid >> 3, cb = (tid & 7) * 4;
            const float* p0 = sa0 + row * 36 + cb;
            const float* p1 = sa1 + row * 36 + cb;
            const float* p2 = sa2 + row * 36 + cb;
            __half* th = tempH + row * 40 + cb;
#pragma unroll
            for (int j = 0; j < 2; j++) {
                float u = fmaf(w2, p2[2 * j], fmaf(w1, p1[2 * j], w0 * p0[2 * j]));
                float v = fmaf(w2, p2[2 * j + 1], fmaf(w1, p1[2 * j + 1], w0 * p0[2 * j + 1]));
                *(__half2*)(th + 2 * j) = __floats2half2_rn(u, v);
            }
        }
        __syncthreads();
        // stream temp chunk to global (coalesced 16B stores, 128 threads)
        if (tid < 128) {
            int row = tid >> 2, cb = (tid & 3) * 8;
            uint4 v = *(const uint4*)(tempH + row * 40 + cb);
            *(uint4*)(Tout + (size_t)(row0 + row) * NN + k0 + cb) = v;
        }
        // P1 mma (fp16)
#pragma unroll
        for (int ks = 0; ks < 2; ks++) {
            int kb = ks * 16;
            uint32_t a[4];
            a[0] = *(const uint32_t*)(tempH + (wm + r) * 40 + kb + q * 2);
            a[1] = *(const uint32_t*)(tempH + (wm + r + 8) * 40 + kb + q * 2);
            a[2] = *(const uint32_t*)(tempH + (wm + r) * 40 + kb + 8 + q * 2);
            a[3] = *(const uint32_t*)(tempH + (wm + r + 8) * 40 + kb + 8 + q * 2);
#pragma unroll
            for (int nt = 0; nt < 4; nt++) {
                int n = wn + nt * 8 + r;
                uint32_t b0 = *(const uint32_t*)(xs + n * 40 + kb + q * 2);
                uint32_t b1 = *(const uint32_t*)(xs + n * 40 + kb + 8 + q * 2);
                mma16(acc[nt], a, b0, b1);
            }
        }
        // fused F_k = A_k @ tok_k (tf32, warps 0-1 cover 32 rows)
        if (warp < 2) {
#pragma unroll
            for (int ks8 = 0; ks8 < 4; ks8++) {
                int kb = ks8 * 8;
                int i0 = (wm + r) * 36 + kb + q;
                int i1 = (wm + r + 8) * 36 + kb + q;
                float af[3][4];
                af[0][0] = sa0[i0]; af[0][1] = sa0[i1]; af[0][2] = sa0[i0 + 4]; af[0][3] = sa0[i1 + 4];
                af[1][0] = sa1[i0]; af[1][1] = sa1[i1]; af[1][2] = sa1[i0 + 4]; af[1][3] = sa1[i1 + 4];
                af[2][0] = sa2[i0]; af[2][1] = sa2[i1]; af[2][2] = sa2[i0 + 4]; af[2][3] = sa2[i1 + 4];
#pragma unroll
                for (int m = 0; m < 3; m++) {
                    uint32_t am[4];
#pragma unroll
                    for (int i = 0; i < 4; i++) am[i] = f2tf32(af[m][i]);
#pragma unroll
                    for (int nt = 0; nt < 2; nt++) {
                        int col = m * 16 + nt * 8 + r;
                        uint32_t b0 = f2tf32(st[(kb + q) * 56 + col]);
                        uint32_t b1 = f2tf32(st[(kb + q + 4) * 56 + col]);
                        mma8(facc[m][nt], am, b0, b1);
                    }
                }
            }
        }
        __syncthreads();
    }
    // epilogue: P1
#pragma unroll
    for (int nt = 0; nt < 4; nt++) {
        int n = wn + nt * 8 + q * 2;
        float2 v0 = {acc[nt][0], acc[nt][1]};
        float2 v1 = {acc[nt][2], acc[nt][3]};
        *(float2*)&P[(size_t)(row0 + wm + r) * 128 + n] = v0;
        *(float2*)&P[(size_t)(row0 + wm + r + 8) * 128 + n] = v1;
    }
    // epilogue: F
    if (warp < 2) {
#pragma unroll
        for (int m = 0; m < 3; m++) {
            float* Fm = F + (size_t)m * NN * 10;
#pragma unroll
            for (int nt = 0; nt < 2; nt++) {
                int t = nt * 8 + q * 2;
                size_t ra = (size_t)(row0 + wm + r) * 10;
                size_t rb = (size_t)(row0 + wm + r + 8) * 10;
                if (t < 10) { Fm[ra + t] = facc[m][nt][0]; Fm[rb + t] = facc[m][nt][2]; }
                if (t + 1 < 10) { Fm[ra + t + 1] = facc[m][nt][1]; Fm[rb + t + 1] = facc[m][nt][3]; }
            }
        }
    }
}

// =============== fp16 temp sweep: C_part = T(^T) @ Xh over one K segment ===============
// grid (128, NSEG), 2-stage pipeline, 4 CTAs/SM.
#define SW_SMEM (2 * 27648)

template <bool TRANS>
__global__ void __launch_bounds__(256, 4)
sweep_k(const __half* __restrict__ Th, const __half* __restrict__ Xh, float* __restrict__ C) {
    extern __shared__ char sm[];
    const int tid = threadIdx.x, lane = tid & 31, warp = tid >> 5;
    const int m0 = blockIdx.x * 64;
    const int kbase = blockIdx.y * SEGK;
    const int wm = (warp & 3) * 16, wn = (warp >> 2) * 64;
    const int r = lane >> 2, q = lane & 3;
    C += (size_t)blockIdx.y * NM;

    float acc[8][4] = {};
    auto Ts = [&](int s) { return (__half*)(sm + s * 27648); };
    auto Xs = [&](int s) { return (__half*)(sm + s * 27648 + 9216); };

    auto load = [&](int s, int k0) {
        __half* ts = Ts(s);
        __half* xs = Xs(s);
#pragma unroll
        for (int it = 0; it < 2; it++) {
            int idx = tid + it * 256;
            int row = idx >> 3, c = idx & 7;
            const __half* src = TRANS ? Th + (size_t)(k0 + row) * NN + m0 + c * 8
                                      : Th + (size_t)(m0 + row) * NN + k0 + c * 8;
            cp16(ts + row * 72 + c * 8, src);
        }
#pragma unroll
        for (int it = 0; it < 4; it++) {
            int idx = tid + it * 256;
            int row = idx >> 3, c = idx & 7;
            cp16(xs + row * 72 + c * 8, Xh + (size_t)row * NN + k0 + c * 8);
        }
        cp_commit();
    };

    load(0, kbase);
#pragma unroll 1
    for (int ch = 0; ch < NCH2; ch++) {
        if (ch + 1 < NCH2) { load((ch + 1) & 1, kbase + (ch + 1) * KCH2); cp_wait<1>(); }
        else { cp_wait<0>(); }
        __syncthreads();
        const __half* ts = Ts(ch & 1);
        const __half* xs = Xs(ch & 1);
#pragma unroll
        for (int ks = 0; ks < 4; ks++) {
            int kb = ks * 16;
            uint32_t a[4];
            if (TRANS) {
                int g = lane >> 3, l8 = lane & 7;
                int rrow = kb + ((g >> 1) << 3) + l8;
                int ccol = wm + ((g & 1) << 3);
                uint32_t addr = (uint32_t)__cvta_generic_to_shared(ts + rrow * 72 + ccol);
                asm volatile(
                    "ldmatrix.sync.aligned.m8n8.x4.trans.shared.b16 {%0,%1,%2,%3}, [%4];"
                    : "=r"(a[0]), "=r"(a[1]), "=r"(a[2]), "=r"(a[3]) : "r"(addr));
            } else {
                a[0] = *(const uint32_t*)(ts + (wm + r) * 72 + kb + q * 2);
                a[1] = *(const uint32_t*)(ts + (wm + r + 8) * 72 + kb + q * 2);
                a[2] = *(const uint32_t*)(ts + (wm + r) * 72 + kb + 8 + q * 2);
                a[3] = *(const uint32_t*)(ts + (wm + r + 8) * 72 + kb + 8 + q * 2);
            }
#pragma unroll
            for (int nt = 0; nt < 8; nt++) {
                int n = wn + nt * 8 + r;
                uint32_t b0 = *(const uint32_t*)(xs + n * 72 + kb + q * 2);
                uint32_t b1 = *(const uint32_t*)(xs + n * 72 + kb + 8 + q * 2);
                mma16(acc[nt], a, b0, b1);
            }
        }
        __syncthreads();
    }
#pragma unroll
    for (int nt = 0; nt < 8; nt++) {
        int n = wn + nt * 8 + q * 2;
        float2 v0 = {acc[nt][0], acc[nt][1]};
        float2 v1 = {acc[nt][2], acc[nt][3]};
        *(float2*)&C[(size_t)(m0 + wm + r) * 128 + n] = v0;
        *(float2*)&C[(size_t)(m0 + wm + r + 8) * 128 + n] = v1;
    }
}

// ---------------- elementwise ----------------
__global__ void u1_k(const float* __restrict__ b1) {
    int i = blockIdx.x * 256 + threadIdx.x;
    float q = g_Qp[i] + g_Qp[NM + i] + g_Qp[2 * NM + i] + g_Qp[3 * NM + i];
    g_U1[i] = g_P1[i] + q + b1[i & 127];
}
__global__ void out_k(const float* __restrict__ b2, float* __restrict__ out) {
    int i = blockIdx.x * 256 + threadIdx.x;
    float p = g_Pp[i] + g_Pp[NM + i] + g_Pp[2 * NM + i] + g_Pp[3 * NM + i];
    float q = g_Qp[i] + g_Qp[NM + i] + g_Qp[2 * NM + i] + g_Qp[3 * NM + i];
    out[i] = 0.5f * (g_U1[i] + (p + q + b2[i & 127]));
}

// ---------------- launch ----------------
extern "C" void kernel_launch(void* const* d_in, const int* in_sizes, int n_in,
                              void* d_out, int out_size) {
    (void)in_sizes; (void)n_in; (void)out_size;
    const float* feature = (const float*)d_in[0];
    const float* A1 = (const float*)d_in[1];
    const float* A2 = (const float*)d_in[2];
    const float* A3 = (const float*)d_in[3];
    const float* t1 = (const float*)d_in[4];
    const float* t2 = (const float*)d_in[5];
    const float* t3 = (const float*)d_in[6];
    const float* wb = (const float*)d_in[7];
    const float* W1 = (const float*)d_in[8];
    const float* b1 = (const float*)d_in[9];
    const float* W2 = (const float*)d_in[10];
    const float* b2 = (const float*)d_in[11];
    float* out = (float*)d_out;

    float *X1p, *X2p, *U1p, *P1p, *Qpp, *Ppp;
    __half *XhT1p, *XhT2p, *Tp;
    cudaGetSymbolAddress((void**)&X1p, g_X1);
    cudaGetSymbolAddress((void**)&X2p, g_X2);
    cudaGetSymbolAddress((void**)&U1p, g_U1);
    cudaGetSymbolAddress((void**)&P1p, g_P1);
    cudaGetSymbolAddress((void**)&Qpp, g_Qp);
    cudaGetSymbolAddress((void**)&Ppp, g_Pp);
    cudaGetSymbolAddress((void**)&XhT1p, g_XhT1);
    cudaGetSymbolAddress((void**)&XhT2p, g_XhT2);
    cudaGetSymbolAddress((void**)&Tp, g_temph);

    cudaFuncSetAttribute(row1_k, cudaFuncAttributeMaxDynamicSharedMemorySize, K1_SMEM);
    cudaFuncSetAttribute(sweep_k<true>, cudaFuncAttributeMaxDynamicSharedMemorySize, SW_SMEM);
    cudaFuncSetAttribute(sweep_k<false>, cudaFuncAttributeMaxDynamicSharedMemorySize, SW_SMEM);

    dim3 sg(128, NSEG);

    pack_tok_k<<<(NN * 48 + 255) / 256, 256>>>(t1, t2, t3);
    gemm_nn_128<256><<<128, 256>>>(feature, W1, X1p);
    xt_k<<<dim3(NN / 32, 4), dim3(32, 8)>>>(X1p, XhT1p);
    // stage 1: row sweep over A (writes temp fp16, P1, F)
    row1_k<<<NN / 32, 256, K1_SMEM>>>(A1, A2, A3, XhT1p, wb, P1p, out + (size_t)NM, Tp);
    // stage 1: col sweep over temp fp16 -> Q1 partials
    sweep_k<true><<<sg, 256, SW_SMEM>>>(Tp, XhT1p, Qpp);
    u1_k<<<NM / 256, 256>>>(b1);
    gemm_nn_128<128><<<128, 256>>>(U1p, W2, X2p);
    xt_k<<<dim3(NN / 32, 4), dim3(32, 8)>>>(X2p, XhT2p);
    // stage 2: row + col sweeps over temp fp16 -> P2/Q2 partials
    sweep_k<false><<<sg, 256, SW_SMEM>>>(Tp, XhT2p, Ppp);
    sweep_k<true><<<sg, 256, SW_SMEM>>>(Tp, XhT2p, Qpp);
    out_k<<<NM / 256, 256>>>(b2, out);
}

// round 14
// speedup vs baseline: 3.0815x; 1.0709x over previous
#include <cuda_runtime.h>
#include <cuda_fp16.h>
#include <cstdint>
#include <cstddef>

#define NN 8192
#define NM (NN * 128)

// K1 (stage-1 row sweep over A): 32-row tiles, grid 256
#define KCH1 32
#define NCH1 (NN / KCH1)
// fp16 temp sweeps: 4 K-segments, 2-stage pipeline
#define NSEG 4
#define SEGK (NN / NSEG)
#define KCH2 64
#define NCH2 (SEGK / KCH2)

// ---------------- scratch (no allocations allowed) ----------------
__device__ float  g_X1[NM];
__device__ float  g_X2[NM];
__device__ float  g_U1[NM];
__device__ float  g_P1[NM];
__device__ float  g_Qp[NSEG * NM];
__device__ float  g_Pp[NSEG * NM];
__device__ __half g_XhT1[128 * NN];
__device__ __half g_XhT2[128 * NN];
__device__ __half g_temph[(size_t)NN * NN];      // 128 MB
__device__ __half g_ptokh[48 * NN];              // tokT fp16: [m*16+t][k], t<10 valid

// ---------------- helpers ----------------
__device__ __forceinline__ void cp16(void* s, const void* g) {
    uint32_t sa = (uint32_t)__cvta_generic_to_shared(s);
    asm volatile("cp.async.cg.shared.global [%0], [%1], 16;" :: "r"(sa), "l"(g));
}
__device__ __forceinline__ void cp_commit() { asm volatile("cp.async.commit_group;"); }
template <int n> __device__ __forceinline__ void cp_wait() {
    asm volatile("cp.async.wait_group %0;" :: "n"(n));
}
// fp16 mma m16n8k16, fp32 accum
__device__ __forceinline__ void mma16(float* c, const uint32_t* a, uint32_t b0, uint32_t b1) {
    asm volatile(
        "mma.sync.aligned.m16n8k16.row.col.f32.f16.f16.f32 "
        "{%0,%1,%2,%3},{%4,%5,%6,%7},{%8,%9},{%0,%1,%2,%3};"
        : "+f"(c[0]), "+f"(c[1]), "+f"(c[2]), "+f"(c[3])
        : "r"(a[0]), "r"(a[1]), "r"(a[2]), "r"(a[3]), "r"(b0), "r"(b1));
}

// ---------------- tok packer: tokT fp16 [48][8192] ----------------
__global__ void pack_tok_k(const float* __restrict__ t1, const float* __restrict__ t2,
                           const float* __restrict__ t3) {
    int idx = blockIdx.x * 256 + threadIdx.x;
    if (idx >= 48 * NN) return;
    int row = idx / NN, k = idx % NN;
    int m = row >> 4, t = row & 15;
    const float* src = (m == 0) ? t1 : (m == 1) ? t2 : t3;
    g_ptokh[idx] = (t < 10) ? __float2half_rn(src[k * 10 + t]) : __half(0.0f);
}

// ---------------- exact fp32 GEMM: C[8192x128] = A[8192xK] @ B[Kx128] ----------------
template <int K>
__global__ void __launch_bounds__(256)
gemm_nn_128(const float* __restrict__ A, const float* __restrict__ B, float* __restrict__ C) {
    __shared__ float As[16][68];
    __shared__ float Bs[16][132];
    int tid = threadIdx.x;
    int m0 = blockIdx.x * 64;
    int tx = tid % 16, ty = tid / 16;
    float acc[4][8] = {};
    for (int k0 = 0; k0 < K; k0 += 16) {
        {
            int kk = tid % 16, mm = tid / 16;
#pragma unroll
            for (int p = 0; p < 4; p++) {
                int m = mm + p * 16;
                As[kk][m] = A[(size_t)(m0 + m) * K + k0 + kk];
            }
        }
        {
            int n = tid % 128, kk2 = tid / 128;
#pragma unroll
            for (int p = 0; p < 8; p++)
                Bs[kk2 + p * 2][n] = B[(size_t)(k0 + kk2 + p * 2) * 128 + n];
        }
        __syncthreads();
#pragma unroll
        for (int kk = 0; kk < 16; kk++) {
            float a[4], b[8];
#pragma unroll
            for (int i = 0; i < 4; i++) a[i] = As[kk][ty * 4 + i];
#pragma unroll
            for (int j = 0; j < 8; j++) b[j] = Bs[kk][tx * 8 + j];
#pragma unroll
            for (int i = 0; i < 4; i++)
#pragma unroll
                for (int j = 0; j < 8; j++) acc[i][j] = fmaf(a[i], b[j], acc[i][j]);
        }
        __syncthreads();
    }
#pragma unroll
    for (int i = 0; i < 4; i++) {
        size_t m = (size_t)(m0 + ty * 4 + i);
#pragma unroll
        for (int j = 0; j < 8; j++) C[m * 128 + tx * 8 + j] = acc[i][j];
    }
}

// ---------------- transpose+convert: XhT[n][k] = (half)X[k][n] ----------------
__global__ void xt_k(const float* __restrict__ X, __half* __restrict__ XT) {
    __shared__ float t[32][33];
    int k0 = blockIdx.x * 32, n0 = blockIdx.y * 32;
    int tx = threadIdx.x, ty = threadIdx.y;   // 32 x 8
#pragma unroll
    for (int i = 0; i < 4; i++)
        t[ty + i * 8][tx] = X[(size_t)(k0 + ty + i * 8) * 128 + n0 + tx];
    __syncthreads();
#pragma unroll
    for (int i = 0; i < 4; i++)
        XT[(size_t)(n0 + ty + i * 8) * NN + k0 + tx] = __float2half_rn(t[tx][ty + i * 8]);
}

// =============== K1: stage-1 row sweep (32-row tiles, grid 256, 2 CTA/SM) ===============
// smem (bytes):
//   A fp32 tiles : (s*3+m)*4608               [32 x stride 36]  -> 41472
//   X fp16       : 41472 + s*10240            [128 x stride 40] -> 30720 (ends 72192)
//   tokT fp16    : 72192 + s*3840             [48 x stride 40]  -> 11520 (ends 83712)
//   tempH fp16   : 83712                      [32 x stride 40]  ->  2560 (ends 86272)
//   amh fp16 x3  : 86272 + m*2560             [32 x stride 40]  ->  7680 (ends 93952)
#define K1_SMEM 94208

__global__ void __launch_bounds__(256, 2)
row1_k(const float* __restrict__ A1, const float* __restrict__ A2,
       const float* __restrict__ A3, const __half* __restrict__ XhT,
       const float* __restrict__ wb, float* __restrict__ P,
       float* __restrict__ F, __half* __restrict__ Tout) {
    extern __shared__ char sm[];
    const int tid = threadIdx.x, lane = tid & 31, warp = tid >> 5;
    const int row0 = blockIdx.x * 32;
    const int wm = (warp & 1) * 16, wn = (warp >> 1) * 32;
    const int r = lane >> 2, q = lane & 3;
    const float w0 = wb[0], w1 = wb[1], w2 = wb[2];

    float acc[4][4] = {};
    float facc[2][4] = {};

    auto smA = [&](int s, int m) { return (float*)sm + (s * 3 + m) * 1152; };
    auto smX = [&](int s) { return (__half*)(sm + 41472) + s * 5120; };
    auto smTok = [&](int s) { return (__half*)(sm + 72192) + s * 1920; };
    __half* tempH = (__half*)(sm + 83712);
    __half* amh = (__half*)(sm + 86272);

    auto load = [&](int s, int k0) {
#pragma unroll
        for (int it = 0; it < 3; it++) {
            int idx = tid + it * 256;
            int m = idx >> 8, rem = idx & 255, row = rem >> 3, c = rem & 7;
            const float* ap = (m == 0) ? A1 : (m == 1) ? A2 : A3;
            cp16(smA(s, m) + row * 36 + c * 4,
                 ap + (size_t)(row0 + row) * NN + k0 + c * 4);
        }
#pragma unroll
        for (int it = 0; it < 2; it++) {
            int idx = tid + it * 256;
            int row = idx >> 2, c = idx & 3;
            cp16(smX(s) + row * 40 + c * 8, XhT + (size_t)row * NN + k0 + c * 8);
        }
        if (tid < 192) {
            int c = tid >> 2, kk = (tid & 3) * 8;
            cp16(smTok(s) + c * 40 + kk, g_ptokh + (size_t)c * NN + k0 + kk);
        }
        cp_commit();
    };

    load(0, 0);
    load(1, KCH1);
#pragma unroll 1
    for (int ch = 0; ch < NCH1; ch++) {
        int k0 = ch * KCH1;
        if (ch + 2 < NCH1) { load((ch + 2) % 3, (ch + 2) * KCH1); cp_wait<2>(); }
        else if (ch + 1 < NCH1) { cp_wait<1>(); }
        else { cp_wait<0>(); }
        __syncthreads();
        int s = ch % 3;
        const float* sa0 = smA(s, 0);
        const float* sa1 = smA(s, 1);
        const float* sa2 = smA(s, 2);
        const __half* xs = smX(s);
        const __half* ts = smTok(s);

        // temp = w0*A1 + w1*A2 + w2*A3 -> fp16 smem; also emit fp16 copies of A1..A3
        {
            int row = tid >> 3, cb = (tid & 7) * 4;
            int off = row * 36 + cb;
            float a0v[4], a1v[4], a2v[4];
#pragma unroll
            for (int j = 0; j < 4; j++) {
                a0v[j] = sa0[off + j];
                a1v[j] = sa1[off + j];
                a2v[j] = sa2[off + j];
            }
            int ho = row * 40 + cb;
#pragma unroll
            for (int j = 0; j < 2; j++) {
                float u = fmaf(w2, a2v[2 * j], fmaf(w1, a1v[2 * j], w0 * a0v[2 * j]));
                float v = fmaf(w2, a2v[2 * j + 1], fmaf(w1, a1v[2 * j + 1], w0 * a0v[2 * j + 1]));
                *(__half2*)(tempH + ho + 2 * j) = __floats2half2_rn(u, v);
                *(__half2*)(amh + ho + 2 * j) = __floats2half2_rn(a0v[2 * j], a0v[2 * j + 1]);
                *(__half2*)(amh + 1280 + ho + 2 * j) = __floats2half2_rn(a1v[2 * j], a1v[2 * j + 1]);
                *(__half2*)(amh + 2560 + ho + 2 * j) = __floats2half2_rn(a2v[2 * j], a2v[2 * j + 1]);
            }
        }
        __syncthreads();
        // stream temp chunk to global (coalesced 16B stores, 128 threads)
        if (tid < 128) {
            int row = tid >> 2, cb = (tid & 3) * 8;
            uint4 v = *(const uint4*)(tempH + row * 40 + cb);
            *(uint4*)(Tout + (size_t)(row0 + row) * NN + k0 + cb) = v;
        }
        // P1 mma (fp16): temp @ X
#pragma unroll
        for (int ks = 0; ks < 2; ks++) {
            int kb = ks * 16;
            uint32_t a[4];
            a[0] = *(const uint32_t*)(tempH + (wm + r) * 40 + kb + q * 2);
            a[1] = *(const uint32_t*)(tempH + (wm + r + 8) * 40 + kb + q * 2);
            a[2] = *(const uint32_t*)(tempH + (wm + r) * 40 + kb + 8 + q * 2);
            a[3] = *(const uint32_t*)(tempH + (wm + r + 8) * 40 + kb + 8 + q * 2);
#pragma unroll
            for (int nt = 0; nt < 4; nt++) {
                int n = wn + nt * 8 + r;
                uint32_t b0 = *(const uint32_t*)(xs + n * 40 + kb + q * 2);
                uint32_t b1 = *(const uint32_t*)(xs + n * 40 + kb + 8 + q * 2);
                mma16(acc[nt], a, b0, b1);
            }
        }
        // fused F: warp w<6 handles mat = w>>1, rowtile = w&1 (fp16 mma, ldmatrix A)
        if (warp < 6) {
            int mat = warp >> 1, rt = warp & 1;
            const __half* ah = amh + mat * 1280;
#pragma unroll
            for (int ks = 0; ks < 2; ks++) {
                int kb = ks * 16;
                int g = lane >> 3, l8 = lane & 7;
                int rrow = rt * 16 + ((g & 1) << 3) + l8;
                int ccol = kb + ((g >> 1) << 3);
                uint32_t addr = (uint32_t)__cvta_generic_to_shared(ah + rrow * 40 + ccol);
                uint32_t a[4];
                asm volatile(
                    "ldmatrix.sync.aligned.m8n8.x4.shared.b16 {%0,%1,%2,%3}, [%4];"
                    : "=r"(a[0]), "=r"(a[1]), "=r"(a[2]), "=r"(a[3]) : "r"(addr));
#pragma unroll
                for (int nt = 0; nt < 2; nt++) {
                    int c = mat * 16 + nt * 8 + r;
                    uint32_t b0 = *(const uint32_t*)(ts + c * 40 + kb + q * 2);
                    uint32_t b1 = *(const uint32_t*)(ts + c * 40 + kb + 8 + q * 2);
                    mma16(facc[nt], a, b0, b1);
                }
            }
        }
        __syncthreads();
    }
    // epilogue: P1
#pragma unroll
    for (int nt = 0; nt < 4; nt++) {
        int n = wn + nt * 8 + q * 2;
        float2 v0 = {acc[nt][0], acc[nt][1]};
        float2 v1 = {acc[nt][2], acc[nt][3]};
        *(float2*)&P[(size_t)(row0 + wm + r) * 128 + n] = v0;
        *(float2*)&P[(size_t)(row0 + wm + r + 8) * 128 + n] = v1;
    }
    // epilogue: F
    if (warp < 6) {
        int mat = warp >> 1, rt = warp & 1;
        float* Fm = F + (size_t)mat * NN * 10;
        size_t ra = (size_t)(row0 + rt * 16 + r) * 10;
        size_t rb = (size_t)(row0 + rt * 16 + r + 8) * 10;
#pragma unroll
        for (int nt = 0; nt < 2; nt++) {
            int t = nt * 8 + q * 2;
            if (t < 10) { Fm[ra + t] = facc[nt][0]; Fm[rb + t] = facc[nt][2]; }
            if (t + 1 < 10) { Fm[ra + t + 1] = facc[nt][1]; Fm[rb + t + 1] = facc[nt][3]; }
        }
    }
}

// =============== fp16 temp sweep: C_part = T(^T) @ Xh over one K segment ===============
// grid (128, NSEG), 2-stage pipeline, 4 CTAs/SM.
#define SW_SMEM (2 * 27648)

template <bool TRANS>
__global__ void __launch_bounds__(256, 4)
sweep_k(const __half* __restrict__ Th, const __half* __restrict__ Xh, float* __restrict__ C) {
    extern __shared__ char sm[];
    const int tid = threadIdx.x, lane = tid & 31, warp = tid >> 5;
    const int m0 = blockIdx.x * 64;
    const int kbase = blockIdx.y * SEGK;
    const int wm = (warp & 3) * 16, wn = (warp >> 2) * 64;
    const int r = lane >> 2, q = lane & 3;
    C += (size_t)blockIdx.y * NM;

    float acc[8][4] = {};
    auto Ts = [&](int s) { return (__half*)(sm + s * 27648); };
    auto Xs = [&](int s) { return (__half*)(sm + s * 27648 + 9216); };

    auto load = [&](int s, int k0) {
        __half* ts = Ts(s);
        __half* xs = Xs(s);
#pragma unroll
        for (int it = 0; it < 2; it++) {
            int idx = tid + it * 256;
            int row = idx >> 3, c = idx & 7;
            const __half* src = TRANS ? Th + (size_t)(k0 + row) * NN + m0 + c * 8
                                      : Th + (size_t)(m0 + row) * NN + k0 + c * 8;
            cp16(ts + row * 72 + c * 8, src);
        }
#pragma unroll
        for (int it = 0; it < 4; it++) {
            int idx = tid + it * 256;
            int row = idx >> 3, c = idx & 7;
            cp16(xs + row * 72 + c * 8, Xh + (size_t)row * NN + k0 + c * 8);
        }
        cp_commit();
    };

    load(0, kbase);
#pragma unroll 1
    for (int ch = 0; ch < NCH2; ch++) {
        if (ch + 1 < NCH2) { load((ch + 1) & 1, kbase + (ch + 1) * KCH2); cp_wait<1>(); }
        else { cp_wait<0>(); }
        __syncthreads();
        const __half* ts = Ts(ch & 1);
        const __half* xs = Xs(ch & 1);
#pragma unroll
        for (int ks = 0; ks < 4; ks++) {
            int kb = ks * 16;
            uint32_t a[4];
            if (TRANS) {
                int g = lane >> 3, l8 = lane & 7;
                int rrow = kb + ((g >> 1) << 3) + l8;
                int ccol = wm + ((g & 1) << 3);
                uint32_t addr = (uint32_t)__cvta_generic_to_shared(ts + rrow * 72 + ccol);
                asm volatile(
                    "ldmatrix.sync.aligned.m8n8.x4.trans.shared.b16 {%0,%1,%2,%3}, [%4];"
                    : "=r"(a[0]), "=r"(a[1]), "=r"(a[2]), "=r"(a[3]) : "r"(addr));
            } else {
                a[0] = *(const uint32_t*)(ts + (wm + r) * 72 + kb + q * 2);
                a[1] = *(const uint32_t*)(ts + (wm + r + 8) * 72 + kb + q * 2);
                a[2] = *(const uint32_t*)(ts + (wm + r) * 72 + kb + 8 + q * 2);
                a[3] = *(const uint32_t*)(ts + (wm + r + 8) * 72 + kb + 8 + q * 2);
            }
#pragma unroll
            for (int nt = 0; nt < 8; nt++) {
                int n = wn + nt * 8 + r;
                uint32_t b0 = *(const uint32_t*)(xs + n * 72 + kb + q * 2);
                uint32_t b1 = *(const uint32_t*)(xs + n * 72 + kb + 8 + q * 2);
                mma16(acc[nt], a, b0, b1);
            }
        }
        __syncthreads();
    }
#pragma unroll
    for (int nt = 0; nt < 8; nt++) {
        int n = wn + nt * 8 + q * 2;
        float2 v0 = {acc[nt][0], acc[nt][1]};
        float2 v1 = {acc[nt][2], acc[nt][3]};
        *(float2*)&C[(size_t)(m0 + wm + r) * 128 + n] = v0;
        *(float2*)&C[(size_t)(m0 + wm + r + 8) * 128 + n] = v1;
    }
}

// ---------------- elementwise ----------------
__global__ void u1_k(const float* __restrict__ b1) {
    int i = blockIdx.x * 256 + threadIdx.x;
    float q = g_Qp[i] + g_Qp[NM + i] + g_Qp[2 * NM + i] + g_Qp[3 * NM + i];
    g_U1[i] = g_P1[i] + q + b1[i & 127];
}
__global__ void out_k(const float* __restrict__ b2, float* __restrict__ out) {
    int i = blockIdx.x * 256 + threadIdx.x;
    float p = g_Pp[i] + g_Pp[NM + i] + g_Pp[2 * NM + i] + g_Pp[3 * NM + i];
    float q = g_Qp[i] + g_Qp[NM + i] + g_Qp[2 * NM + i] + g_Qp[3 * NM + i];
    out[i] = 0.5f * (g_U1[i] + (p + q + b2[i & 127]));
}

// ---------------- launch ----------------
extern "C" void kernel_launch(void* const* d_in, const int* in_sizes, int n_in,
                              void* d_out, int out_size) {
    (void)in_sizes; (void)n_in; (void)out_size;
    const float* feature = (const float*)d_in[0];
    const float* A1 = (const float*)d_in[1];
    const float* A2 = (const float*)d_in[2];
    const float* A3 = (const float*)d_in[3];
    const float* t1 = (const float*)d_in[4];
    const float* t2 = (const float*)d_in[5];
    const float* t3 = (const float*)d_in[6];
    const float* wb = (const float*)d_in[7];
    const float* W1 = (const float*)d_in[8];
    const float* b1 = (const float*)d_in[9];
    const float* W2 = (const float*)d_in[10];
    const float* b2 = (const float*)d_in[11];
    float* out = (float*)d_out;

    float *X1p, *X2p, *U1p, *P1p, *Qpp, *Ppp;
    __half *XhT1p, *XhT2p, *Tp;
    cudaGetSymbolAddress((void**)&X1p, g_X1);
    cudaGetSymbolAddress((void**)&X2p, g_X2);
    cudaGetSymbolAddress((void**)&U1p, g_U1);
    cudaGetSymbolAddress((void**)&P1p, g_P1);
    cudaGetSymbolAddress((void**)&Qpp, g_Qp);
    cudaGetSymbolAddress((void**)&Ppp, g_Pp);
    cudaGetSymbolAddress((void**)&XhT1p, g_XhT1);
    cudaGetSymbolAddress((void**)&XhT2p, g_XhT2);
    cudaGetSymbolAddress((void**)&Tp, g_temph);

    cudaFuncSetAttribute(row1_k, cudaFuncAttributeMaxDynamicSharedMemorySize, K1_SMEM);
    cudaFuncSetAttribute(sweep_k<true>, cudaFuncAttributeMaxDynamicSharedMemorySize, SW_SMEM);
    cudaFuncSetAttribute(sweep_k<false>, cudaFuncAttributeMaxDynamicSharedMemorySize, SW_SMEM);

    dim3 sg(128, NSEG);

    pack_tok_k<<<(48 * NN + 255) / 256, 256>>>(t1, t2, t3);
    gemm_nn_128<256><<<128, 256>>>(feature, W1, X1p);
    xt_k<<<dim3(NN / 32, 4), dim3(32, 8)>>>(X1p, XhT1p);
    // stage 1: row sweep over A (writes temp fp16, P1, F)
    row1_k<<<NN / 32, 256, K1_SMEM>>>(A1, A2, A3, XhT1p, wb, P1p, out + (size_t)NM, Tp);
    // stage 1: col sweep over temp fp16 -> Q1 partials
    sweep_k<true><<<sg, 256, SW_SMEM>>>(Tp, XhT1p, Qpp);
    u1_k<<<NM / 256, 256>>>(b1);
    gemm_nn_128<128><<<128, 256>>>(U1p, W2, X2p);
    xt_k<<<dim3(NN / 32, 4), dim3(32, 8)>>>(X2p, XhT2p);
    // stage 2: row + col sweeps over temp fp16 -> P2/Q2 partials
    sweep_k<false><<<sg, 256, SW_SMEM>>>(Tp, XhT2p, Ppp);
    sweep_k<true><<<sg, 256, SW_SMEM>>>(Tp, XhT2p, Qpp);
    out_k<<<NM / 256, 256>>>(b2, out);
}

// round 17
// speedup vs baseline: 3.1175x; 1.0117x over previous
#include <cuda_runtime.h>
#include <cuda_fp16.h>
#include <cstdint>
#include <cstddef>

#define NN 8192
#define NM (NN * 128)

// K1 (stage-1 row sweep over A): 32-row tiles, grid 256, KCH 64, 2-stage
#define KCH1 64
#define NCH1 (NN / KCH1)
// fp16 temp sweeps: 4 K-segments, 2-stage pipeline
#define NSEG 4
#define SEGK (NN / NSEG)
#define KCH2 64
#define NCH2 (SEGK / KCH2)

// ---------------- scratch (no allocations allowed) ----------------
__device__ float  g_X1[NM];
__device__ float  g_X2[NM];
__device__ float  g_U1[NM];
__device__ float  g_P1[NM];
__device__ float  g_Qp[NSEG * NM];
__device__ float  g_Pp[NSEG * NM];
__device__ __half g_XhT1[128 * NN];
__device__ __half g_XhT2[128 * NN];
__device__ __half g_temph[(size_t)NN * NN];      // 128 MB
__device__ __half g_ptokh[48 * NN];              // tokT fp16: [m*16+t][k], t<10 valid

// ---------------- helpers ----------------
__device__ __forceinline__ void cp16(void* s, const void* g) {
    uint32_t sa = (uint32_t)__cvta_generic_to_shared(s);
    asm volatile("cp.async.cg.shared.global [%0], [%1], 16;" :: "r"(sa), "l"(g));
}
__device__ __forceinline__ void cp_commit() { asm volatile("cp.async.commit_group;"); }
template <int n> __device__ __forceinline__ void cp_wait() {
    asm volatile("cp.async.wait_group %0;" :: "n"(n));
}
// fp16 mma m16n8k16, fp32 accum
__device__ __forceinline__ void mma16(float* c, const uint32_t* a, uint32_t b0, uint32_t b1) {
    asm volatile(
        "mma.sync.aligned.m16n8k16.row.col.f32.f16.f16.f32 "
        "{%0,%1,%2,%3},{%4,%5,%6,%7},{%8,%9},{%0,%1,%2,%3};"
        : "+f"(c[0]), "+f"(c[1]), "+f"(c[2]), "+f"(c[3])
        : "r"(a[0]), "r"(a[1]), "r"(a[2]), "r"(a[3]), "r"(b0), "r"(b1));
}
__device__ __forceinline__ uint32_t h2u(__half2 h) {
    return *reinterpret_cast<uint32_t*>(&h);
}

// ---------------- tok packer: tokT fp16 [48][8192] ----------------
__global__ void pack_tok_k(const float* __restrict__ t1, const float* __restrict__ t2,
                           const float* __restrict__ t3) {
    int idx = blockIdx.x * 256 + threadIdx.x;
    if (idx >= 48 * NN) return;
    int row = idx / NN, k = idx % NN;
    int m = row >> 4, t = row & 15;
    const float* src = (m == 0) ? t1 : (m == 1) ? t2 : t3;
    g_ptokh[idx] = (t < 10) ? __float2half_rn(src[k * 10 + t]) : __half(0.0f);
}

// ---------------- exact fp32 GEMM: C[8192x128] = A[8192xK] @ B[Kx128] ----------------
template <int K>
__global__ void __launch_bounds__(256)
gemm_nn_128(const float* __restrict__ A, const float* __restrict__ B, float* __restrict__ C) {
    __shared__ float As[16][68];
    __shared__ float Bs[16][132];
    int tid = threadIdx.x;
    int m0 = blockIdx.x * 64;
    int tx = tid % 16, ty = tid / 16;
    float acc[4][8] = {};
    for (int k0 = 0; k0 < K; k0 += 16) {
        {
            int kk = tid % 16, mm = tid / 16;
#pragma unroll
            for (int p = 0; p < 4; p++) {
                int m = mm + p * 16;
                As[kk][m] = A[(size_t)(m0 + m) * K + k0 + kk];
            }
        }
        {
            int n = tid % 128, kk2 = tid / 128;
#pragma unroll
            for (int p = 0; p < 8; p++)
                Bs[kk2 + p * 2][n] = B[(size_t)(k0 + kk2 + p * 2) * 128 + n];
        }
        __syncthreads();
#pragma unroll
        for (int kk = 0; kk < 16; kk++) {
            float a[4], b[8];
#pragma unroll
            for (int i = 0; i < 4; i++) a[i] = As[kk][ty * 4 + i];
#pragma unroll
            for (int j = 0; j < 8; j++) b[j] = Bs[kk][tx * 8 + j];
#pragma unroll
            for (int i = 0; i < 4; i++)
#pragma unroll
                for (int j = 0; j < 8; j++) acc[i][j] = fmaf(a[i], b[j], acc[i][j]);
        }
        __syncthreads();
    }
#pragma unroll
    for (int i = 0; i < 4; i++) {
        size_t m = (size_t)(m0 + ty * 4 + i);
#pragma unroll
        for (int j = 0; j < 8; j++) C[m * 128 + tx * 8 + j] = acc[i][j];
    }
}

// ---------------- transpose+convert: XhT[n][k] = (half)X[k][n] ----------------
__global__ void xt_k(const float* __restrict__ X, __half* __restrict__ XT) {
    __shared__ float t[32][33];
    int k0 = blockIdx.x * 32, n0 = blockIdx.y * 32;
    int tx = threadIdx.x, ty = threadIdx.y;   // 32 x 8
#pragma unroll
    for (int i = 0; i < 4; i++)
        t[ty + i * 8][tx] = X[(size_t)(k0 + ty + i * 8) * 128 + n0 + tx];
    __syncthreads();
#pragma unroll
    for (int i = 0; i < 4; i++)
        XT[(size_t)(n0 + ty + i * 8) * NN + k0 + tx] = __float2half_rn(t[tx][ty + i * 8]);
}

// =============== K1: stage-1 row sweep (32-row tiles, grid 256, KCH 64, 2 CTA/SM) ===============
// smem (bytes):
//   A fp32 tiles : (s*3+m)*8704   [32 rows x stride 68 floats]  -> 52224
//   X fp16       : 52224 + s*18432 [128 x stride 72 halfs]      -> 36864 (ends 89088)
//   tokT fp16    : 89088 + s*6912  [48 x stride 72]             -> 13824 (ends 102912)
//   tempH fp16   : 102912          [32 x stride 72]             ->  4608 (ends 107520)
#define K1_SMEM 107520

__global__ void __launch_bounds__(256, 2)
row1_k(const float* __restrict__ A1, const float* __restrict__ A2,
       const float* __restrict__ A3, const __half* __restrict__ XhT,
       const float* __restrict__ wb, float* __restrict__ P,
       float* __restrict__ F, __half* __restrict__ Tout) {
    extern __shared__ char sm[];
    const int tid = threadIdx.x, lane = tid & 31, warp = tid >> 5;
    const int row0 = blockIdx.x * 32;
    const int wm = (warp & 1) * 16, wn = (warp >> 1) * 32;
    const int r = lane >> 2, q = lane & 3;
    const float w0 = wb[0], w1 = wb[1], w2 = wb[2];

    float acc[4][4] = {};
    float facc[2][4] = {};

    auto smA = [&](int s, int m) { return (float*)(sm + (s * 3 + m) * 8704); };
    auto smX = [&](int s) { return (__half*)(sm + 52224 + s * 18432); };
    auto smTok = [&](int s) { return (__half*)(sm + 89088 + s * 6912); };
    __half* tempH = (__half*)(sm + 102912);

    auto load = [&](int s, int k0) {
#pragma unroll
        for (int it = 0; it < 6; it++) {
            int u = tid + it * 256;
            int m = u >> 9, rem = u & 511, row = rem >> 4, c = rem & 15;
            const float* ap = (m == 0) ? A1 : (m == 1) ? A2 : A3;
            cp16(smA(s, m) + row * 68 + c * 4,
                 ap + (size_t)(row0 + row) * NN + k0 + c * 4);
        }
#pragma unroll
        for (int it = 0; it < 4; it++) {
            int u = tid + it * 256;
            int row = u >> 3, c = u & 7;
            cp16(smX(s) + row * 72 + c * 8, XhT + (size_t)row * NN + k0 + c * 8);
        }
#pragma unroll
        for (int it = 0; it < 2; it++) {
            int u = tid + it * 256;
            if (u < 384) {
                int row = u >> 3, c = u & 7;
                cp16(smTok(s) + row * 72 + c * 8, g_ptokh + (size_t)row * NN + k0 + c * 8);
            }
        }
        cp_commit();
    };

    load(0, 0);
#pragma unroll 1
    for (int ch = 0; ch < NCH1; ch++) {
        int k0 = ch * KCH1;
        if (ch + 1 < NCH1) { load((ch + 1) & 1, k0 + KCH1); cp_wait<1>(); }
        else { cp_wait<0>(); }
        __syncthreads();
        int s = ch & 1;
        const float* sa0 = smA(s, 0);
        const float* sa1 = smA(s, 1);
        const float* sa2 = smA(s, 2);
        const __half* xs = smX(s);
        const __half* ts = smTok(s);

        // combine: temp = w0*A1 + w1*A2 + w2*A3 (8 floats/thread) -> tempH smem + Tout global
        {
            int row = tid >> 3, cb = (tid & 7) * 8;
            int off = row * 68 + cb;
            float4 u0 = *(const float4*)(sa0 + off);
            float4 u1 = *(const float4*)(sa0 + off + 4);
            float4 v0 = *(const float4*)(sa1 + off);
            float4 v1 = *(const float4*)(sa1 + off + 4);
            float4 x0 = *(const float4*)(sa2 + off);
            float4 x1 = *(const float4*)(sa2 + off + 4);
            float c0 = fmaf(w2, x0.x, fmaf(w1, v0.x, w0 * u0.x));
            float c1 = fmaf(w2, x0.y, fmaf(w1, v0.y, w0 * u0.y));
            float c2 = fmaf(w2, x0.z, fmaf(w1, v0.z, w0 * u0.z));
            float c3 = fmaf(w2, x0.w, fmaf(w1, v0.w, w0 * u0.w));
            float c4 = fmaf(w2, x1.x, fmaf(w1, v1.x, w0 * u1.x));
            float c5 = fmaf(w2, x1.y, fmaf(w1, v1.y, w0 * u1.y));
            float c6 = fmaf(w2, x1.z, fmaf(w1, v1.z, w0 * u1.z));
            float c7 = fmaf(w2, x1.w, fmaf(w1, v1.w, w0 * u1.w));
            uint4 pk;
            pk.x = h2u(__floats2half2_rn(c0, c1));
            pk.y = h2u(__floats2half2_rn(c2, c3));
            pk.z = h2u(__floats2half2_rn(c4, c5));
            pk.w = h2u(__floats2half2_rn(c6, c7));
            *(uint4*)(tempH + row * 72 + cb) = pk;
            *(uint4*)(Tout + (size_t)(row0 + row) * NN + k0 + cb) = pk;
        }
        __syncthreads();
        // P1 mma (fp16): temp @ X  (4 k-steps of 16)
#pragma unroll
        for (int ks = 0; ks < 4; ks++) {
            int kb = ks * 16;
            uint32_t a[4];
            a[0] = *(const uint32_t*)(tempH + (wm + r) * 72 + kb + q * 2);
            a[1] = *(const uint32_t*)(tempH + (wm + r + 8) * 72 + kb + q * 2);
            a[2] = *(const uint32_t*)(tempH + (wm + r) * 72 + kb + 8 + q * 2);
            a[3] = *(const uint32_t*)(tempH + (wm + r + 8) * 72 + kb + 8 + q * 2);
#pragma unroll
            for (int nt = 0; nt < 4; nt++) {
                int n = wn + nt * 8 + r;
                uint32_t b0 = *(const uint32_t*)(xs + n * 72 + kb + q * 2);
                uint32_t b1 = *(const uint32_t*)(xs + n * 72 + kb + 8 + q * 2);
                mma16(acc[nt], a, b0, b1);
            }
        }
        // fused F: warp w<6: mat = w>>1, rowtile = w&1; fragments from fp32 A smem
        if (warp < 6) {
            int mat = warp >> 1, rt = warp & 1;
            const float* ah = (mat == 0) ? sa0 : (mat == 1) ? sa1 : sa2;
#pragma unroll
            for (int ks = 0; ks < 4; ks++) {
                int kb = ks * 16;
                uint32_t a[4];
                {
                    float2 f0 = *(const float2*)(ah + (rt * 16 + r) * 68 + kb + q * 2);
                    float2 f1 = *(const float2*)(ah + (rt * 16 + r + 8) * 68 + kb + q * 2);
                    float2 f2 = *(const float2*)(ah + (rt * 16 + r) * 68 + kb + 8 + q * 2);
                    float2 f3 = *(const float2*)(ah + (rt * 16 + r + 8) * 68 + kb + 8 + q * 2);
                    a[0] = h2u(__floats2half2_rn(f0.x, f0.y));
                    a[1] = h2u(__floats2half2_rn(f1.x, f1.y));
                    a[2] = h2u(__floats2half2_rn(f2.x, f2.y));
                    a[3] = h2u(__floats2half2_rn(f3.x, f3.y));
                }
#pragma unroll
                for (int nt = 0; nt < 2; nt++) {
                    int c = mat * 16 + nt * 8 + r;
                    uint32_t b0 = *(const uint32_t*)(ts + c * 72 + kb + q * 2);
                    uint32_t b1 = *(const uint32_t*)(ts + c * 72 + kb + 8 + q * 2);
                    mma16(facc[nt], a, b0, b1);
                }
            }
        }
        __syncthreads();
    }
    // epilogue: P1
#pragma unroll
    for (int nt = 0; nt < 4; nt++) {
        int n = wn + nt * 8 + q * 2;
        float2 v0 = {acc[nt][0], acc[nt][1]};
        float2 v1 = {acc[nt][2], acc[nt][3]};
        *(float2*)&P[(size_t)(row0 + wm + r) * 128 + n] = v0;
        *(float2*)&P[(size_t)(row0 + wm + r + 8) * 128 + n] = v1;
    }
    // epilogue: F
    if (warp < 6) {
        int mat = warp >> 1, rt = warp & 1;
        float* Fm = F + (size_t)mat * NN * 10;
        size_t ra = (size_t)(row0 + rt * 16 + r) * 10;
        size_t rb = (size_t)(row0 + rt * 16 + r + 8) * 10;
#pragma unroll
        for (int nt = 0; nt < 2; nt++) {
            int t = nt * 8 + q * 2;
            if (t < 10) { Fm[ra + t] = facc[nt][0]; Fm[rb + t] = facc[nt][2]; }
            if (t + 1 < 10) { Fm[ra + t + 1] = facc[nt][1]; Fm[rb + t + 1] = facc[nt][3]; }
        }
    }
}

// =============== fp16 temp sweep: C_part = T(^T) @ Xh over one K segment ===============
// grid (128, NSEG), 2-stage pipeline, 4 CTAs/SM.
#define SW_SMEM (2 * 27648)

template <bool TRANS>
__global__ void __launch_bounds__(256, 4)
sweep_k(const __half* __restrict__ Th, const __half* __restrict__ Xh, float* __restrict__ C) {
    extern __shared__ char sm[];
    const int tid = threadIdx.x, lane = tid & 31, warp = tid >> 5;
    const int m0 = blockIdx.x * 64;
    const int kbase = blockIdx.y * SEGK;
    const int wm = (warp & 3) * 16, wn = (warp >> 2) * 64;
    const int r = lane >> 2, q = lane & 3;
    C += (size_t)blockIdx.y * NM;

    float acc[8][4] = {};
    auto Ts = [&](int s) { return (__half*)(sm + s * 27648); };
    auto Xs = [&](int s) { return (__half*)(sm + s * 27648 + 9216); };

    auto load = [&](int s, int k0) {
        __half* ts = Ts(s);
        __half* xs = Xs(s);
#pragma unroll
        for (int it = 0; it < 2; it++) {
            int idx = tid + it * 256;
            int row = idx >> 3, c = idx & 7;
            const __half* src = TRANS ? Th + (size_t)(k0 + row) * NN + m0 + c * 8
                                      : Th + (size_t)(m0 + row) * NN + k0 + c * 8;
            cp16(ts + row * 72 + c * 8, src);
        }
#pragma unroll
        for (int it = 0; it < 4; it++) {
            int idx = tid + it * 256;
            int row = idx >> 3, c = idx & 7;
            cp16(xs + row * 72 + c * 8, Xh + (size_t)row * NN + k0 + c * 8);
        }
        cp_commit();
    };

    load(0, kbase);
#pragma unroll 1
    for (int ch = 0; ch < NCH2; ch++) {
        if (ch + 1 < NCH2) { load((ch + 1) & 1, kbase + (ch + 1) * KCH2); cp_wait<1>(); }
        else { cp_wait<0>(); }
        __syncthreads();
        const __half* ts = Ts(ch & 1);
        const __half* xs = Xs(ch & 1);
#pragma unroll
        for (int ks = 0; ks < 4; ks++) {
            int kb = ks * 16;
            uint32_t a[4];
            if (TRANS) {
                int g = lane >> 3, l8 = lane & 7;
                int rrow = kb + ((g >> 1) << 3) + l8;
                int ccol = wm + ((g & 1) << 3);
                uint32_t addr = (uint32_t)__cvta_generic_to_shared(ts + rrow * 72 + ccol);
                asm volatile(
                    "ldmatrix.sync.aligned.m8n8.x4.trans.shared.b16 {%0,%1,%2,%3}, [%4];"
                    : "=r"(a[0]), "=r"(a[1]), "=r"(a[2]), "=r"(a[3]) : "r"(addr));
            } else {
                a[0] = *(const uint32_t*)(ts + (wm + r) * 72 + kb + q * 2);
                a[1] = *(const uint32_t*)(ts + (wm + r + 8) * 72 + kb + q * 2);
                a[2] = *(const uint32_t*)(ts + (wm + r) * 72 + kb + 8 + q * 2);
                a[3] = *(const uint32_t*)(ts + (wm + r + 8) * 72 + kb + 8 + q * 2);
            }
#pragma unroll
            for (int nt = 0; nt < 8; nt++) {
                int n = wn + nt * 8 + r;
                uint32_t b0 = *(const uint32_t*)(xs + n * 72 + kb + q * 2);
                uint32_t b1 = *(const uint32_t*)(xs + n * 72 + kb + 8 + q * 2);
                mma16(acc[nt], a, b0, b1);
            }
        }
        __syncthreads();
    }
#pragma unroll
    for (int nt = 0; nt < 8; nt++) {
        int n = wn + nt * 8 + q * 2;
        float2 v0 = {acc[nt][0], acc[nt][1]};
        float2 v1 = {acc[nt][2], acc[nt][3]};
        *(float2*)&C[(size_t)(m0 + wm + r) * 128 + n] = v0;
        *(float2*)&C[(size_t)(m0 + wm + r + 8) * 128 + n] = v1;
    }
}

// ---------------- elementwise ----------------
__global__ void u1_k(const float* __restrict__ b1) {
    int i = blockIdx.x * 256 + threadIdx.x;
    float q = g_Qp[i] + g_Qp[NM + i] + g_Qp[2 * NM + i] + g_Qp[3 * NM + i];
    g_U1[i] = g_P1[i] + q + b1[i & 127];
}
__global__ void out_k(const float* __restrict__ b2, float* __restrict__ out) {
    int i = blockIdx.x * 256 + threadIdx.x;
    float p = g_Pp[i] + g_Pp[NM + i] + g_Pp[2 * NM + i] + g_Pp[3 * NM + i];
    float q = g_Qp[i] + g_Qp[NM + i] + g_Qp[2 * NM + i] + g_Qp[3 * NM + i];
    out[i] = 0.5f * (g_U1[i] + (p + q + b2[i & 127]));
}

// ---------------- launch ----------------
extern "C" void kernel_launch(void* const* d_in, const int* in_sizes, int n_in,
                              void* d_out, int out_size) {
    (void)in_sizes; (void)n_in; (void)out_size;
    const float* feature = (const float*)d_in[0];
    const float* A1 = (const float*)d_in[1];
    const float* A2 = (const float*)d_in[2];
    const float* A3 = (const float*)d_in[3];
    const float* t1 = (const float*)d_in[4];
    const float* t2 = (const float*)d_in[5];
    const float* t3 = (const float*)d_in[6];
    const float* wb = (const float*)d_in[7];
    const float* W1 = (const float*)d_in[8];
    const float* b1 = (const float*)d_in[9];
    const float* W2 = (const float*)d_in[10];
    const float* b2 = (const float*)d_in[11];
    float* out = (float*)d_out;

    float *X1p, *X2p, *U1p, *P1p, *Qpp, *Ppp;
    __half *XhT1p, *XhT2p, *Tp;
    cudaGetSymbolAddress((void**)&X1p, g_X1);
    cudaGetSymbolAddress((void**)&X2p, g_X2);
    cudaGetSymbolAddress((void**)&U1p, g_U1);
    cudaGetSymbolAddress((void**)&P1p, g_P1);
    cudaGetSymbolAddress((void**)&Qpp, g_Qp);
    cudaGetSymbolAddress((void**)&Ppp, g_Pp);
    cudaGetSymbolAddress((void**)&XhT1p, g_XhT1);
    cudaGetSymbolAddress((void**)&XhT2p, g_XhT2);
    cudaGetSymbolAddress((void**)&Tp, g_temph);

    cudaFuncSetAttribute(row1_k, cudaFuncAttributeMaxDynamicSharedMemorySize, K1_SMEM);
    cudaFuncSetAttribute(sweep_k<true>, cudaFuncAttributeMaxDynamicSharedMemorySize, SW_SMEM);
    cudaFuncSetAttribute(sweep_k<false>, cudaFuncAttributeMaxDynamicSharedMemorySize, SW_SMEM);

    dim3 sg(128, NSEG);

    pack_tok_k<<<(48 * NN + 255) / 256, 256>>>(t1, t2, t3);
    gemm_nn_128<256><<<128, 256>>>(feature, W1, X1p);
    xt_k<<<dim3(NN / 32, 4), dim3(32, 8)>>>(X1p, XhT1p);
    // stage 1: row sweep over A (writes temp fp16, P1, F)
    row1_k<<<NN / 32, 256, K1_SMEM>>>(A1, A2, A3, XhT1p, wb, P1p, out + (size_t)NM, Tp);
    // stage 1: col sweep over temp fp16 -> Q1 partials
    sweep_k<true><<<sg, 256, SW_SMEM>>>(Tp, XhT1p, Qpp);
    u1_k<<<NM / 256, 256>>>(b1);
    gemm_nn_128<128><<<128, 256>>>(U1p, W2, X2p);
    xt_k<<<dim3(NN / 32, 4), dim3(32, 8)>>>(X2p, XhT2p);
    // stage 2: row + col sweeps over temp fp16 -> P2/Q2 partials
    sweep_k<false><<<sg, 256, SW_SMEM>>>(Tp, XhT2p, Ppp);
    sweep_k<true><<<sg, 256, SW_SMEM>>>(Tp, XhT2p, Qpp);
    out_k<<<NM / 256, 256>>>(b2, out);
}